// round 12
// baseline (speedup 1.0000x reference)
#include <cuda_runtime.h>
#include <cuda_fp16.h>
#include <math.h>
#include <stdint.h>

#define S_LEN 2048
#define HID   2048
#define NHEADS 32
#define HDIM   64
#define QDIM  2048
#define KVDIM  512
#define VD     128
#define LAMBDA_INIT 0.7455692280263552f

// ---------------- scratch ----------------
__device__ float g_O[(size_t)NHEADS * S_LEN * VD];
__device__ float g_lam;
__device__ __align__(256) __half g_H16[(size_t)S_LEN * HID];
__device__ __align__(256) __half g_Wq16[(size_t)QDIM * HID];
__device__ __align__(256) __half g_Wk16[(size_t)KVDIM * HID];
__device__ __align__(256) __half g_Wv16[(size_t)KVDIM * HID];
__device__ __align__(256) __half g_Wo16[(size_t)HID * QDIM];
__device__ __align__(256) __half g_Ac16[(size_t)S_LEN * QDIM];
__device__ __align__(256) __half g_Q16[(size_t)S_LEN * QDIM];
__device__ __align__(256) __half g_K16[(size_t)S_LEN * KVDIM];
__device__ __align__(256) __half g_Vt16[(size_t)KVDIM * S_LEN];   // transposed [d][s]

// ---------------- helpers ----------------
__device__ __forceinline__ uint32_t smem_u32(const void* p) {
  uint32_t r;
  asm("{ .reg .u64 t; cvta.to.shared.u64 t, %1; cvt.u32.u64 %0, t; }" : "=r"(r) : "l"(p));
  return r;
}
#define CP_ASYNC16(sa, ga) \
  asm volatile("cp.async.cg.shared.global [%0], [%1], 16;" :: "r"(sa), "l"(ga) : "memory")
#define CP_COMMIT() asm volatile("cp.async.commit_group;" ::: "memory")
#define CP_WAIT0()  asm volatile("cp.async.wait_group 0;" ::: "memory")

#define LDMATRIX_X4(r0, r1, r2, r3, addr) \
  asm volatile("ldmatrix.sync.aligned.m8n8.x4.shared.b16 {%0,%1,%2,%3}, [%4];" \
               : "=r"(r0), "=r"(r1), "=r"(r2), "=r"(r3) : "r"(addr))

#define MMA16816H(c0, c1, c2, c3, a0, a1, a2, a3, b0, b1) \
  asm volatile("mma.sync.aligned.m16n8k16.row.col.f32.f16.f16.f32 " \
               "{%0,%1,%2,%3}, {%4,%5,%6,%7}, {%8,%9}, {%0,%1,%2,%3};" \
               : "+f"(c0), "+f"(c1), "+f"(c2), "+f"(c3) \
               : "r"(a0), "r"(a1), "r"(a2), "r"(a3), "r"(b0), "r"(b1))

__device__ __forceinline__ uint32_t pack2h(float a, float b) {
  __half2 h = __floats2half2_rn(a, b);
  return *(uint32_t*)&h;
}

// ---------------- GEMM config ----------------
#define GROWB 144
#define GTILE (128 * GROWB)
#define GSTAGE (2 * GTILE)
#define GSMEM (2 * GSTAGE)   // 73728

// mainloop macro body shared by both GEMM kernels (acc in regs)
#define HGEMM_MAINLOOP(Aptr, Bptr, Kc)                                          \
  const int warp = tid >> 5;                                                    \
  const int lane = tid & 31;                                                    \
  const int wm = warp & 1;                                                      \
  const int wn = warp >> 1;                                                     \
  const uint32_t sb = smem_u32(sm);                                             \
  const int lrow = tid >> 1;                                                    \
  const int lch0 = (tid & 1) << 2;                                              \
  float acc[4][4][4];                                                           \
  _Pragma("unroll")                                                             \
  for (int i = 0; i < 4; i++)                                                   \
    _Pragma("unroll")                                                           \
    for (int j = 0; j < 4; j++)                                                 \
      _Pragma("unroll")                                                         \
      for (int c = 0; c < 4; c++) acc[i][j][c] = 0.f;                           \
  const int nT = (Kc) >> 6;                                                     \
  auto load_stage_g = [&](int k0, uint32_t st) {                                \
    const __half* ag = (Aptr) + (size_t)(m0 + lrow) * (Kc) + k0 + lch0 * 8;     \
    const __half* bg = (Bptr) + (size_t)(n0 + lrow) * (Kc) + k0 + lch0 * 8;     \
    uint32_t so = st + lrow * GROWB + lch0 * 16;                                \
    _Pragma("unroll")                                                           \
    for (int c = 0; c < 4; c++) {                                               \
      CP_ASYNC16(so + c * 16, ag + c * 8);                                      \
      CP_ASYNC16(so + GTILE + c * 16, bg + c * 8);                              \
    }                                                                           \
  };                                                                            \
  load_stage_g(0, sb);                                                          \
  CP_COMMIT();                                                                  \
  for (int t = 0; t < nT; ++t) {                                                \
    CP_WAIT0();                                                                 \
    __syncthreads();                                                            \
    const uint32_t cur = sb + (uint32_t)(t & 1) * GSTAGE;                       \
    if (t + 1 < nT) {                                                           \
      load_stage_g((t + 1) << 6, sb + (uint32_t)((t + 1) & 1) * GSTAGE);        \
      CP_COMMIT();                                                              \
    }                                                                           \
    _Pragma("unroll")                                                           \
    for (int ks = 0; ks < 4; ++ks) {                                            \
      uint32_t a[4][4];                                                         \
      _Pragma("unroll")                                                         \
      for (int mi = 0; mi < 4; ++mi) {                                          \
        uint32_t addr = cur + (uint32_t)((wm << 6) + (mi << 4) + (lane & 15)) * GROWB \
                        + ((lane >> 4) << 4) + (ks << 5);                       \
        LDMATRIX_X4(a[mi][0], a[mi][1], a[mi][2], a[mi][3], addr);              \
      }                                                                         \
      uint32_t b[4][2];                                                         \
      _Pragma("unroll")                                                         \
      for (int pr = 0; pr < 2; ++pr) {                                          \
        int r = (lane & 7) + (((lane >> 4) & 1) << 3);                          \
        int hk = (lane >> 3) & 1;                                               \
        uint32_t addr = cur + GTILE + (uint32_t)((wn << 5) + (pr << 4) + r) * GROWB \
                        + (hk << 4) + (ks << 5);                                \
        uint32_t r0, r1, r2, r3;                                                \
        LDMATRIX_X4(r0, r1, r2, r3, addr);                                      \
        b[pr * 2 + 0][0] = r0; b[pr * 2 + 0][1] = r1;                           \
        b[pr * 2 + 1][0] = r2; b[pr * 2 + 1][1] = r3;                           \
      }                                                                         \
      _Pragma("unroll")                                                         \
      for (int mi = 0; mi < 4; ++mi)                                            \
        _Pragma("unroll")                                                       \
        for (int ni = 0; ni < 4; ++ni)                                          \
          MMA16816H(acc[mi][ni][0], acc[mi][ni][1], acc[mi][ni][2], acc[mi][ni][3], \
                    a[mi][0], a[mi][1], a[mi][2], a[mi][3], b[ni][0], b[ni][1]); \
    }                                                                           \
  }

// ---------------- fused QKV GEMM + RoPE + fp16 + V-transpose ----------------
// Flat grid of 384 CTAs: [0,256) Q, [256,320) K, [320,384) V.
__global__ __launch_bounds__(256, 2) void hgemm_qkv_fused(
    const __half* __restrict__ H16,
    const __half* __restrict__ Wq16, const __half* __restrict__ Wk16,
    const __half* __restrict__ Wv16,
    const float* __restrict__ cosb, const float* __restrict__ sinb,
    __half* __restrict__ Q16, __half* __restrict__ K16, __half* __restrict__ Vt16) {
  extern __shared__ char sm[];
  const int tid = threadIdx.x;
  const int bid = blockIdx.x;
  int z, n0, m0;
  if (bid < 256)      { z = 0; n0 = (bid & 15) << 7; m0 = (bid >> 4) << 7; }
  else if (bid < 320) { int u = bid - 256; z = 1; n0 = (u & 3) << 7; m0 = (u >> 2) << 7; }
  else                { int u = bid - 320; z = 2; n0 = (u & 3) << 7; m0 = (u >> 2) << 7; }
  const __half* Bp = (z == 0) ? Wq16 : (z == 1) ? Wk16 : Wv16;

  HGEMM_MAINLOOP(H16, Bp, HID)

  // ---- epilogue: stage fp32 -> smem [128][132] ----
  __syncthreads();   // all warps done with pipeline smem
  float* stage = (float*)sm;
#pragma unroll
  for (int mi = 0; mi < 4; ++mi) {
    int rl = (wm << 6) + (mi << 4) + (lane >> 2);
#pragma unroll
    for (int ni = 0; ni < 4; ++ni) {
      int cl = (wn << 5) + (ni << 3) + ((lane & 3) << 1);
      *(float2*)(stage + rl * 132 + cl)       = make_float2(acc[mi][ni][0], acc[mi][ni][1]);
      *(float2*)(stage + (rl + 8) * 132 + cl) = make_float2(acc[mi][ni][2], acc[mi][ni][3]);
    }
  }
  __syncthreads();

  const int rl = tid >> 1;
  const int hf = tid & 1;
  if (z < 2) {
    // RoPE + fp16: thread owns one full 64-d head of one row
    const int s = m0 + rl;
    const int width = (z == 0) ? QDIM : KVDIM;
    __half* dst = ((z == 0) ? Q16 : K16) + (size_t)s * width + n0 + hf * 64;
    const float* xr = stage + rl * 132 + hf * 64;
    const float* cr = cosb + (size_t)s * HDIM;
    const float* sr = sinb + (size_t)s * HDIM;
#pragma unroll
    for (int c2 = 0; c2 < 2; c2++) {
      const int d0 = c2 * 16;
      uint32_t lo[8], hi[8];
#pragma unroll
      for (int i = 0; i < 16; i += 2) {
        int d = d0 + i;
        float xa0 = xr[d],      xa1 = xr[d + 1];
        float xb0 = xr[d + 32], xb1 = xr[d + 33];
        float ya0 = xa0 * cr[d]      - xb0 * sr[d];
        float ya1 = xa1 * cr[d + 1]  - xb1 * sr[d + 1];
        float yb0 = xb0 * cr[d + 32] + xa0 * sr[d + 32];
        float yb1 = xb1 * cr[d + 33] + xa1 * sr[d + 33];
        lo[i >> 1] = pack2h(ya0, ya1);
        hi[i >> 1] = pack2h(yb0, yb1);
      }
      *(uint4*)(dst + d0)      = make_uint4(lo[0], lo[1], lo[2], lo[3]);
      *(uint4*)(dst + d0 + 8)  = make_uint4(lo[4], lo[5], lo[6], lo[7]);
      *(uint4*)(dst + d0 + 32) = make_uint4(hi[0], hi[1], hi[2], hi[3]);
      *(uint4*)(dst + d0 + 40) = make_uint4(hi[4], hi[5], hi[6], hi[7]);
    }
  } else {
    // V transpose + fp16: thread owns one output column (feature), 64 s-values
    const int cl = rl;                 // local feature col 0..127
    const int sh = hf * 64;            // s-half
    __half* dst = Vt16 + (size_t)(n0 + cl) * S_LEN + m0 + sh;
#pragma unroll
    for (int c4 = 0; c4 < 4; c4++) {
      uint32_t p[8];
#pragma unroll
      for (int i = 0; i < 16; i += 2) {
        float v0 = stage[(sh + c4 * 16 + i) * 132 + cl];
        float v1 = stage[(sh + c4 * 16 + i + 1) * 132 + cl];
        p[i >> 1] = pack2h(v0, v1);
      }
      *(uint4*)(dst + c4 * 16)     = make_uint4(p[0], p[1], p[2], p[3]);
      *(uint4*)(dst + c4 * 16 + 8) = make_uint4(p[4], p[5], p[6], p[7]);
    }
  }
}

// ---------------- O-projection GEMM (plain fp16, fp32 out) ----------------
__global__ __launch_bounds__(256, 2) void hgemm_o_kernel(
    const __half* __restrict__ Ac16, const __half* __restrict__ Wo16,
    float* __restrict__ out) {
  extern __shared__ char sm[];
  const int tid = threadIdx.x;
  const int n0 = blockIdx.x << 7;
  const int m0 = blockIdx.y << 7;

  HGEMM_MAINLOOP(Ac16, Wo16, QDIM)

#pragma unroll
  for (int mi = 0; mi < 4; ++mi) {
    int row = m0 + (wm << 6) + (mi << 4) + (lane >> 2);
#pragma unroll
    for (int ni = 0; ni < 4; ++ni) {
      int col = n0 + (wn << 5) + (ni << 3) + ((lane & 3) << 1);
      *(float2*)(out + (size_t)row * HID + col)       = make_float2(acc[mi][ni][0], acc[mi][ni][1]);
      *(float2*)(out + (size_t)(row + 8) * HID + col) = make_float2(acc[mi][ni][2], acc[mi][ni][3]);
    }
  }
}

// ---------------- fp32 -> fp16 convert ----------------
__global__ void f2h_kernel(const float* __restrict__ x, __half* __restrict__ o, int total) {
  int i4 = (blockIdx.x * blockDim.x + threadIdx.x) << 2;
  if (i4 >= total) return;
  float4 v = *(const float4*)(x + i4);
  uint2 ph;
  ph.x = (uint32_t)__half_as_ushort(__float2half_rn(v.x)) |
         ((uint32_t)__half_as_ushort(__float2half_rn(v.y)) << 16);
  ph.y = (uint32_t)__half_as_ushort(__float2half_rn(v.z)) |
         ((uint32_t)__half_as_ushort(__float2half_rn(v.w)) << 16);
  *(uint2*)(o + i4) = ph;
}

// ---------------- lambda ----------------
__global__ void lam_kernel(const float* __restrict__ lq1, const float* __restrict__ lk1,
                           const float* __restrict__ lq2, const float* __restrict__ lk2) {
  int d = threadIdx.x;
  float s1 = lq1[d] * lk1[d] + lq1[d + 32] * lk1[d + 32];
  float s2 = lq2[d] * lk2[d] + lq2[d + 32] * lk2[d + 32];
#pragma unroll
  for (int off = 16; off > 0; off >>= 1) {
    s1 += __shfl_xor_sync(0xffffffffu, s1, off);
    s2 += __shfl_xor_sync(0xffffffffu, s2, off);
  }
  if (d == 0) g_lam = expf(s1) - expf(s2) + LAMBDA_INIT;
}

// ---------------- HMMA flash attention: plain fp16 ----------------
#define ATT_ST   18432
#define ATT_STGB 27648
#define ATT_SMEM (18432 + 2 * 27648)    // 73728

__global__ __launch_bounds__(256, 2) void flash_attn_hmma(
    const __half* __restrict__ Q16, const __half* __restrict__ K16,
    const __half* __restrict__ Vt16, float* __restrict__ O) {
  extern __shared__ char sm[];
  const uint32_t sb = smem_u32(sm);
  const int tid = threadIdx.x;
  const int w = tid >> 5, lane = tid & 31;
  const int h = blockIdx.y;
  const int qb = 15 - (int)blockIdx.x;
  const int q0 = qb << 7;
  const int kh = h >> 2;
  const int ii = h & 15;
  const int vh0 = ii >> 2, vh1 = 4 + (ii >> 2);
  const int nk = 2 * qb + 2;

  auto load_stage = [&](int k0, uint32_t stg) {
#pragma unroll
    for (int i = 0; i < 6; i++) {
      int id = tid + (i << 8);
      if (id < 512) {
        int row = id >> 3, ch = id & 7;
        const __half* src = K16 + (size_t)(k0 + row) * KVDIM + kh * HDIM + ch * 8;
        CP_ASYNC16(stg + row * 144 + ch * 16, src);
      } else {
        int t = id - 512;
        int row = t >> 3, ch = t & 7;
        int grow = (row < 64) ? (vh0 * HDIM + row) : (vh1 * HDIM + row - 64);
        const __half* src = Vt16 + (size_t)grow * S_LEN + k0 + ch * 8;
        CP_ASYNC16(stg + 9216 + row * 144 + ch * 16, src);
      }
    }
  };

  {
#pragma unroll
    for (int i = 0; i < 4; i++) {
      int id = tid + (i << 8);
      int row = id >> 3, ch = id & 7;
      const __half* src = Q16 + (size_t)(q0 + row) * QDIM + h * HDIM + ch * 8;
      CP_ASYNC16(sb + row * 144 + ch * 16, src);
    }
    load_stage(0, sb + ATT_ST);
    CP_COMMIT();
    CP_WAIT0();
  }
  __syncthreads();

  uint32_t qf[4][4];
#pragma unroll
  for (int s = 0; s < 4; s++) {
    uint32_t a = sb + (uint32_t)(w * 16 + (lane & 15)) * 144 + ((lane >> 4) << 4) + s * 32;
    LDMATRIX_X4(qf[s][0], qf[s][1], qf[s][2], qf[s][3], a);
  }

  float oacc[16][4];
#pragma unroll
  for (int n = 0; n < 16; n++)
#pragma unroll
    for (int c = 0; c < 4; c++) oacc[n][c] = 0.f;
  float m0r = -1e30f, m1r = -1e30f, l0r = 0.f, l1r = 0.f;
  const int rmin = q0 + w * 16;
  const int rmax = rmin + 15;
  const int r0g = rmin + (lane >> 2);
  const int r1g = r0g + 8;

  for (int kb = 0; kb < nk; kb++) {
    const int k0 = kb << 6;
    const uint32_t stg = sb + ATT_ST + (uint32_t)(kb & 1) * ATT_STGB;
    if (kb + 1 < nk) {
      load_stage((kb + 1) << 6, sb + ATT_ST + (uint32_t)((kb + 1) & 1) * ATT_STGB);
      CP_COMMIT();
    }

    if (k0 <= rmax) {
      float sacc[8][4];
#pragma unroll
      for (int j = 0; j < 8; j++)
#pragma unroll
        for (int c = 0; c < 4; c++) sacc[j][c] = 0.f;

#pragma unroll
      for (int j = 0; j < 8; j++) {
        uint32_t bh[2][4];
#pragma unroll
        for (int s2 = 0; s2 < 2; s2++) {
          uint32_t a = stg + (uint32_t)(j * 8 + (lane & 7)) * 144 + s2 * 64 + ((lane >> 3) & 3) * 16;
          LDMATRIX_X4(bh[s2][0], bh[s2][1], bh[s2][2], bh[s2][3], a);
        }
#pragma unroll
        for (int s = 0; s < 4; s++) {
          uint32_t b0 = bh[s >> 1][(s & 1) * 2], b1 = bh[s >> 1][(s & 1) * 2 + 1];
          MMA16816H(sacc[j][0], sacc[j][1], sacc[j][2], sacc[j][3],
                    qf[s][0], qf[s][1], qf[s][2], qf[s][3], b0, b1);
        }
      }

      const bool needmask = (k0 + 63) > rmin;
#pragma unroll
      for (int j = 0; j < 8; j++) {
        int cb = k0 + j * 8 + ((lane & 3) << 1);
        sacc[j][0] *= 0.125f; sacc[j][1] *= 0.125f;
        sacc[j][2] *= 0.125f; sacc[j][3] *= 0.125f;
        if (needmask) {
          if (cb     > r0g) sacc[j][0] = -1e30f;
          if (cb + 1 > r0g) sacc[j][1] = -1e30f;
          if (cb     > r1g) sacc[j][2] = -1e30f;
          if (cb + 1 > r1g) sacc[j][3] = -1e30f;
        }
      }

      float mx0 = -1e30f, mx1 = -1e30f;
#pragma unroll
      for (int j = 0; j < 8; j++) {
        mx0 = fmaxf(mx0, fmaxf(sacc[j][0], sacc[j][1]));
        mx1 = fmaxf(mx1, fmaxf(sacc[j][2], sacc[j][3]));
      }
      mx0 = fmaxf(mx0, __shfl_xor_sync(0xffffffffu, mx0, 1));
      mx0 = fmaxf(mx0, __shfl_xor_sync(0xffffffffu, mx0, 2));
      mx1 = fmaxf(mx1, __shfl_xor_sync(0xffffffffu, mx1, 1));
      mx1 = fmaxf(mx1, __shfl_xor_sync(0xffffffffu, mx1, 2));
      float mn0 = fmaxf(m0r, mx0), mn1 = fmaxf(m1r, mx1);
      float al0 = __expf(m0r - mn0), al1 = __expf(m1r - mn1);
      m0r = mn0; m1r = mn1;

      float sum0 = 0.f, sum1 = 0.f;
      uint32_t ph[8][2];
#pragma unroll
      for (int j = 0; j < 8; j++) {
        float p0 = __expf(sacc[j][0] - mn0);
        float p1 = __expf(sacc[j][1] - mn0);
        float p2 = __expf(sacc[j][2] - mn1);
        float p3 = __expf(sacc[j][3] - mn1);
        sum0 += p0 + p1; sum1 += p2 + p3;
        ph[j][0] = pack2h(p0, p1);
        ph[j][1] = pack2h(p2, p3);
      }
      sum0 += __shfl_xor_sync(0xffffffffu, sum0, 1);
      sum0 += __shfl_xor_sync(0xffffffffu, sum0, 2);
      sum1 += __shfl_xor_sync(0xffffffffu, sum1, 1);
      sum1 += __shfl_xor_sync(0xffffffffu, sum1, 2);
      l0r = l0r * al0 + sum0;
      l1r = l1r * al1 + sum1;
#pragma unroll
      for (int n = 0; n < 16; n++) {
        oacc[n][0] *= al0; oacc[n][1] *= al0;
        oacc[n][2] *= al1; oacc[n][3] *= al1;
      }

#pragma unroll
      for (int n = 0; n < 16; n++) {
        uint32_t vh[2][4];
#pragma unroll
        for (int s2 = 0; s2 < 2; s2++) {
          uint32_t a = stg + 9216 + (uint32_t)(n * 8 + (lane & 7)) * 144 + s2 * 64 + ((lane >> 3) & 3) * 16;
          LDMATRIX_X4(vh[s2][0], vh[s2][1], vh[s2][2], vh[s2][3], a);
        }
#pragma unroll
        for (int t = 0; t < 4; t++) {
          uint32_t a0 = ph[2 * t][0], a1 = ph[2 * t][1], a2 = ph[2 * t + 1][0], a3 = ph[2 * t + 1][1];
          uint32_t b0 = vh[t >> 1][(t & 1) * 2], b1 = vh[t >> 1][(t & 1) * 2 + 1];
          MMA16816H(oacc[n][0], oacc[n][1], oacc[n][2], oacc[n][3], a0, a1, a2, a3, b0, b1);
        }
      }
    }

    CP_WAIT0();
    __syncthreads();
  }

  float i0 = 1.f / l0r, i1 = 1.f / l1r;
#pragma unroll
  for (int n = 0; n < 16; n++) {
    int col = n * 8 + ((lane & 3) << 1);
    *(float2*)(O + ((size_t)h * S_LEN + r0g) * VD + col) = make_float2(oacc[n][0] * i0, oacc[n][1] * i0);
    *(float2*)(O + ((size_t)h * S_LEN + r1g) * VD + col) = make_float2(oacc[n][2] * i1, oacc[n][3] * i1);
  }
}

// ---------------- differential combine + RMS norm -> single fp16 ----------------
__global__ void combine_kernel(const float* __restrict__ O, __half* __restrict__ Ac16) {
  const int s = blockIdx.x;
  const int i = blockIdx.y;
  const int d = threadIdx.x;
  const float lam = g_lam;
  float o1 = O[((size_t)i * S_LEN + s) * VD + d];
  float o2 = O[((size_t)(i + 16) * S_LEN + s) * VD + d];
  float a = o1 - lam * o2;
  float ss = a * a;
#pragma unroll
  for (int off = 16; off > 0; off >>= 1)
    ss += __shfl_xor_sync(0xffffffffu, ss, off);
  __shared__ float ws[4];
  int warp = d >> 5, lane = d & 31;
  if (lane == 0) ws[warp] = ss;
  __syncthreads();
  float tot = ws[0] + ws[1] + ws[2] + ws[3];
  float r = rsqrtf(tot * (1.0f / 128.0f) + 1e-6f);
  float aval = (1.0f - LAMBDA_INIT) * a * r;
  Ac16[(size_t)s * QDIM + i * VD + d] = __float2half_rn(aval);
}

// ---------------- launch ----------------
extern "C" void kernel_launch(void* const* d_in, const int* in_sizes, int n_in,
                              void* d_out, int out_size) {
  const float* hidden = (const float*)d_in[0];
  const float* cosb   = (const float*)d_in[1];
  const float* sinb   = (const float*)d_in[2];
  const float* Wq     = (const float*)d_in[3];
  const float* Wk     = (const float*)d_in[4];
  const float* Wv     = (const float*)d_in[5];
  const float* Wo     = (const float*)d_in[6];
  const float* lq1    = (const float*)d_in[7];
  const float* lk1    = (const float*)d_in[8];
  const float* lq2    = (const float*)d_in[9];
  const float* lk2    = (const float*)d_in[10];
  float* out = (float*)d_out;

  float* Op;
  cudaGetSymbolAddress((void**)&Op, g_O);
  __half *H16, *Wq16, *Wk16, *Wv16, *Wo16, *Ac16;
  cudaGetSymbolAddress((void**)&H16, g_H16);
  cudaGetSymbolAddress((void**)&Wq16, g_Wq16);
  cudaGetSymbolAddress((void**)&Wk16, g_Wk16);
  cudaGetSymbolAddress((void**)&Wv16, g_Wv16);
  cudaGetSymbolAddress((void**)&Wo16, g_Wo16);
  cudaGetSymbolAddress((void**)&Ac16, g_Ac16);
  __half *Q16p, *K16p, *Vt16p;
  cudaGetSymbolAddress((void**)&Q16p, g_Q16);
  cudaGetSymbolAddress((void**)&K16p, g_K16);
  cudaGetSymbolAddress((void**)&Vt16p, g_Vt16);

  cudaFuncSetAttribute(hgemm_qkv_fused, cudaFuncAttributeMaxDynamicSharedMemorySize, GSMEM);
  cudaFuncSetAttribute(hgemm_o_kernel,  cudaFuncAttributeMaxDynamicSharedMemorySize, GSMEM);
  cudaFuncSetAttribute(flash_attn_hmma, cudaFuncAttributeMaxDynamicSharedMemorySize, ATT_SMEM);

  // converts (fp32 -> fp16)
  {
    int n = S_LEN * HID;
    f2h_kernel<<<n / 4 / 256, 256>>>(hidden, H16, n);
    n = QDIM * HID;
    f2h_kernel<<<n / 4 / 256, 256>>>(Wq, Wq16, n);
    n = KVDIM * HID;
    f2h_kernel<<<n / 4 / 256, 256>>>(Wk, Wk16, n);
    f2h_kernel<<<n / 4 / 256, 256>>>(Wv, Wv16, n);
    n = HID * QDIM;
    f2h_kernel<<<n / 4 / 256, 256>>>(Wo, Wo16, n);
  }

  // lambda (independent, launch early)
  lam_kernel<<<1, 32>>>(lq1, lk1, lq2, lk2);

  // fused QKV GEMM + RoPE + fp16 + V-transpose
  hgemm_qkv_fused<<<384, 256, GSMEM>>>(H16, Wq16, Wk16, Wv16, cosb, sinb, Q16p, K16p, Vt16p);

  // attention (plain fp16 HMMA)
  flash_attn_hmma<<<dim3(16, NHEADS), 256, ATT_SMEM>>>(Q16p, K16p, Vt16p, Op);

  // combine + RMS norm -> fp16 A
  combine_kernel<<<dim3(S_LEN, 16), 128>>>(Op, Ac16);

  // output projection (plain fp16)
  hgemm_o_kernel<<<dim3(QDIM / 128, S_LEN / 128), 256, GSMEM>>>(Ac16, Wo16, out);
}

// round 14
// speedup vs baseline: 1.0299x; 1.0299x over previous
#include <cuda_runtime.h>
#include <cuda_fp16.h>
#include <math.h>
#include <stdint.h>

#define S_LEN 2048
#define HID   2048
#define NHEADS 32
#define HDIM   64
#define QDIM  2048
#define KVDIM  512
#define VD     128
#define LAMBDA_INIT 0.7455692280263552f

// ---------------- scratch ----------------
__device__ float g_Q[(size_t)S_LEN * QDIM];
__device__ float g_K[(size_t)S_LEN * KVDIM];
__device__ float g_V[(size_t)S_LEN * KVDIM];
__device__ float g_O[(size_t)NHEADS * S_LEN * VD];
__device__ float g_lam;
__device__ __align__(256) __half g_H16[(size_t)S_LEN * HID];
__device__ __align__(256) __half g_Wq16[(size_t)QDIM * HID];
__device__ __align__(256) __half g_Wk16[(size_t)KVDIM * HID];
__device__ __align__(256) __half g_Wv16[(size_t)KVDIM * HID];
__device__ __align__(256) __half g_Wo16[(size_t)HID * QDIM];
__device__ __align__(256) __half g_Ac16[(size_t)S_LEN * QDIM];
__device__ __align__(256) __half g_Q16[(size_t)S_LEN * QDIM];
__device__ __align__(256) __half g_K16[(size_t)S_LEN * KVDIM];
__device__ __align__(256) __half g_Vt16[(size_t)KVDIM * S_LEN];

// ---------------- helpers ----------------
__device__ __forceinline__ uint32_t smem_u32(const void* p) {
  uint32_t r;
  asm("{ .reg .u64 t; cvta.to.shared.u64 t, %1; cvt.u32.u64 %0, t; }" : "=r"(r) : "l"(p));
  return r;
}
#define CP_ASYNC16(sa, ga) \
  asm volatile("cp.async.cg.shared.global [%0], [%1], 16;" :: "r"(sa), "l"(ga) : "memory")
#define CP_COMMIT() asm volatile("cp.async.commit_group;" ::: "memory")
#define CP_WAIT0()  asm volatile("cp.async.wait_group 0;" ::: "memory")

#define LDMATRIX_X4(r0, r1, r2, r3, addr) \
  asm volatile("ldmatrix.sync.aligned.m8n8.x4.shared.b16 {%0,%1,%2,%3}, [%4];" \
               : "=r"(r0), "=r"(r1), "=r"(r2), "=r"(r3) : "r"(addr))

#define MMA16816H(c0, c1, c2, c3, a0, a1, a2, a3, b0, b1) \
  asm volatile("mma.sync.aligned.m16n8k16.row.col.f32.f16.f16.f32 " \
               "{%0,%1,%2,%3}, {%4,%5,%6,%7}, {%8,%9}, {%0,%1,%2,%3};" \
               : "+f"(c0), "+f"(c1), "+f"(c2), "+f"(c3) \
               : "r"(a0), "r"(a1), "r"(a2), "r"(a3), "r"(b0), "r"(b1))

__device__ __forceinline__ uint32_t pack2h(float a, float b) {
  __half2 h = __floats2half2_rn(a, b);
  return *(uint32_t*)&h;
}

// ---------------- fp16 HMMA GEMM: C[M,N] = A[M,Kc] @ B[N,Kc]^T ----------------
#define GROWB 144
#define GTILE (128 * GROWB)
#define GSTAGE (2 * GTILE)
#define GSMEM (2 * GSTAGE)

__device__ __forceinline__ void hgemm_core(
    const __half* __restrict__ A, const __half* __restrict__ B,
    float* __restrict__ C, int N, int Kc, int m0, int n0, char* sm) {
  const int tid = threadIdx.x;
  const int warp = tid >> 5;
  const int lane = tid & 31;
  const int wm = warp & 1;
  const int wn = warp >> 1;
  const uint32_t sb = smem_u32(sm);

  const int lrow = tid >> 1;
  const int lch0 = (tid & 1) << 2;

  float acc[4][4][4];
#pragma unroll
  for (int i = 0; i < 4; i++)
#pragma unroll
    for (int j = 0; j < 4; j++)
#pragma unroll
      for (int c = 0; c < 4; c++) acc[i][j][c] = 0.f;

  const int nT = Kc >> 6;

  auto load_stage = [&](int k0, uint32_t st) {
    const __half* ag = A + (size_t)(m0 + lrow) * Kc + k0 + lch0 * 8;
    const __half* bg = B + (size_t)(n0 + lrow) * Kc + k0 + lch0 * 8;
    uint32_t so = st + lrow * GROWB + lch0 * 16;
#pragma unroll
    for (int c = 0; c < 4; c++) {
      CP_ASYNC16(so + c * 16, ag + c * 8);
      CP_ASYNC16(so + GTILE + c * 16, bg + c * 8);
    }
  };

  load_stage(0, sb);
  CP_COMMIT();

  for (int t = 0; t < nT; ++t) {
    CP_WAIT0();
    __syncthreads();
    const uint32_t cur = sb + (uint32_t)(t & 1) * GSTAGE;
    if (t + 1 < nT) {
      load_stage((t + 1) << 6, sb + (uint32_t)((t + 1) & 1) * GSTAGE);
      CP_COMMIT();
    }

#pragma unroll
    for (int ks = 0; ks < 4; ++ks) {
      uint32_t a[4][4];
#pragma unroll
      for (int mi = 0; mi < 4; ++mi) {
        uint32_t addr = cur + (uint32_t)((wm << 6) + (mi << 4) + (lane & 15)) * GROWB
                        + ((lane >> 4) << 4) + (ks << 5);
        LDMATRIX_X4(a[mi][0], a[mi][1], a[mi][2], a[mi][3], addr);
      }
      uint32_t b[4][2];
#pragma unroll
      for (int pr = 0; pr < 2; ++pr) {
        int r = (lane & 7) + (((lane >> 4) & 1) << 3);
        int hk = (lane >> 3) & 1;
        uint32_t addr = cur + GTILE + (uint32_t)((wn << 5) + (pr << 4) + r) * GROWB
                        + (hk << 4) + (ks << 5);
        uint32_t r0, r1, r2, r3;
        LDMATRIX_X4(r0, r1, r2, r3, addr);
        b[pr * 2 + 0][0] = r0; b[pr * 2 + 0][1] = r1;
        b[pr * 2 + 1][0] = r2; b[pr * 2 + 1][1] = r3;
      }
#pragma unroll
      for (int mi = 0; mi < 4; ++mi)
#pragma unroll
        for (int ni = 0; ni < 4; ++ni)
          MMA16816H(acc[mi][ni][0], acc[mi][ni][1], acc[mi][ni][2], acc[mi][ni][3],
                    a[mi][0], a[mi][1], a[mi][2], a[mi][3], b[ni][0], b[ni][1]);
    }
  }

#pragma unroll
  for (int mi = 0; mi < 4; ++mi) {
    int row = m0 + (wm << 6) + (mi << 4) + (lane >> 2);
#pragma unroll
    for (int ni = 0; ni < 4; ++ni) {
      int col = n0 + (wn << 5) + (ni << 3) + ((lane & 3) << 1);
      *(float2*)(C + (size_t)row * N + col)       = make_float2(acc[mi][ni][0], acc[mi][ni][1]);
      *(float2*)(C + (size_t)(row + 8) * N + col) = make_float2(acc[mi][ni][2], acc[mi][ni][3]);
    }
  }
}

// flat 384-CTA QKV grid: [0,256) Q, [256,320) K, [320,384) V
__global__ __launch_bounds__(256, 2) void hgemm_qkv_kernel(
    const __half* __restrict__ H16,
    const __half* __restrict__ Wq16, const __half* __restrict__ Wk16,
    const __half* __restrict__ Wv16,
    float* __restrict__ Qo, float* __restrict__ Ko, float* __restrict__ Vo) {
  extern __shared__ char sm[];
  const int bid = blockIdx.x;
  const __half* Bp;
  float* C;
  int N, n0, m0;
  if (bid < 256)      { Bp = Wq16; C = Qo; N = QDIM;  n0 = (bid & 15) << 7;        m0 = (bid >> 4) << 7; }
  else if (bid < 320) { int u = bid - 256; Bp = Wk16; C = Ko; N = KVDIM; n0 = (u & 3) << 7; m0 = (u >> 2) << 7; }
  else                { int u = bid - 320; Bp = Wv16; C = Vo; N = KVDIM; n0 = (u & 3) << 7; m0 = (u >> 2) << 7; }
  hgemm_core(H16, Bp, C, N, HID, m0, n0, sm);
}

__global__ __launch_bounds__(256, 2) void hgemm_o_kernel(
    const __half* __restrict__ Ac16, const __half* __restrict__ Wo16,
    float* __restrict__ out) {
  extern __shared__ char sm[];
  hgemm_core(Ac16, Wo16, out, HID, QDIM, blockIdx.y << 7, blockIdx.x << 7, sm);
}

// ---------------- fp32 -> fp16 convert ----------------
__global__ void f2h_kernel(const float* __restrict__ x, __half* __restrict__ o, int total) {
  int i4 = (blockIdx.x * blockDim.x + threadIdx.x) << 2;
  if (i4 >= total) return;
  float4 v = *(const float4*)(x + i4);
  uint2 ph;
  ph.x = (uint32_t)__half_as_ushort(__float2half_rn(v.x)) |
         ((uint32_t)__half_as_ushort(__float2half_rn(v.y)) << 16);
  ph.y = (uint32_t)__half_as_ushort(__float2half_rn(v.z)) |
         ((uint32_t)__half_as_ushort(__float2half_rn(v.w)) << 16);
  *(uint2*)(o + i4) = ph;
}

// ---------------- RoPE -> single fp16 ----------------
__global__ void rope_h16_kernel(const float* __restrict__ X, const float* __restrict__ cosb,
                                const float* __restrict__ sinb,
                                __half* __restrict__ X16, int width) {
  int idx = blockIdx.x * blockDim.x + threadIdx.x;
  int pairsPerRow = width >> 1;
  int total = S_LEN * pairsPerRow;
  if (idx >= total) return;
  int s = idx / pairsPerRow;
  int p = idx - s * pairsPerRow;
  int head = p >> 5;
  int d = p & 31;
  int c1 = head * HDIM + d;
  float c   = cosb[s * HDIM + d];
  float sn  = sinb[s * HDIM + d];
  float c2  = cosb[s * HDIM + d + 32];
  float sn2 = sinb[s * HDIM + d + 32];
  size_t base = (size_t)s * width;
  float x1 = X[base + c1];
  float x2 = X[base + c1 + 32];
  X16[base + c1]      = __float2half_rn(x1 * c  - x2 * sn);
  X16[base + c1 + 32] = __float2half_rn(x2 * c2 + x1 * sn2);
}

// ---------------- V transpose -> single fp16: Vt[d][s] ----------------
__global__ void vt16_kernel(const float* __restrict__ V, __half* __restrict__ Vt16) {
  __shared__ float tile[32][33];
  int c0 = blockIdx.x << 5;
  int s0 = blockIdx.y << 5;
  int tx = threadIdx.x, ty = threadIdx.y;
#pragma unroll
  for (int i = 0; i < 4; i++)
    tile[ty + i * 8][tx] = V[(size_t)(s0 + ty + i * 8) * KVDIM + c0 + tx];
  __syncthreads();
#pragma unroll
  for (int i = 0; i < 4; i++) {
    int r = ty + i * 8;
    Vt16[(size_t)(c0 + r) * S_LEN + s0 + tx] = __float2half_rn(tile[tx][r]);
  }
}

// ---------------- lambda ----------------
__global__ void lam_kernel(const float* __restrict__ lq1, const float* __restrict__ lk1,
                           const float* __restrict__ lq2, const float* __restrict__ lk2) {
  int d = threadIdx.x;
  float s1 = lq1[d] * lk1[d] + lq1[d + 32] * lk1[d + 32];
  float s2 = lq2[d] * lk2[d] + lq2[d + 32] * lk2[d + 32];
#pragma unroll
  for (int off = 16; off > 0; off >>= 1) {
    s1 += __shfl_xor_sync(0xffffffffu, s1, off);
    s2 += __shfl_xor_sync(0xffffffffu, s2, off);
  }
  if (d == 0) g_lam = expf(s1) - expf(s2) + LAMBDA_INIT;
}

// ---------------- HMMA flash attention: plain fp16 ----------------
#define ATT_ST   18432
#define ATT_STGB 27648
#define ATT_SMEM (18432 + 2 * 27648)    // 73728

__global__ __launch_bounds__(256, 2) void flash_attn_hmma(
    const __half* __restrict__ Q16, const __half* __restrict__ K16,
    const __half* __restrict__ Vt16, float* __restrict__ O) {
  extern __shared__ char sm[];
  const uint32_t sb = smem_u32(sm);
  const int tid = threadIdx.x;
  const int w = tid >> 5, lane = tid & 31;
  const int h = blockIdx.y;
  const int qb = 15 - (int)blockIdx.x;
  const int q0 = qb << 7;
  const int kh = h >> 2;
  const int ii = h & 15;
  const int vh0 = ii >> 2, vh1 = 4 + (ii >> 2);
  const int nk = 2 * qb + 2;

  auto load_stage = [&](int k0, uint32_t stg) {
#pragma unroll
    for (int i = 0; i < 6; i++) {
      int id = tid + (i << 8);
      if (id < 512) {
        int row = id >> 3, ch = id & 7;
        const __half* src = K16 + (size_t)(k0 + row) * KVDIM + kh * HDIM + ch * 8;
        CP_ASYNC16(stg + row * 144 + ch * 16, src);
      } else {
        int t = id - 512;
        int row = t >> 3, ch = t & 7;
        int grow = (row < 64) ? (vh0 * HDIM + row) : (vh1 * HDIM + row - 64);
        const __half* src = Vt16 + (size_t)grow * S_LEN + k0 + ch * 8;
        CP_ASYNC16(stg + 9216 + row * 144 + ch * 16, src);
      }
    }
  };

  {
#pragma unroll
    for (int i = 0; i < 4; i++) {
      int id = tid + (i << 8);
      int row = id >> 3, ch = id & 7;
      const __half* src = Q16 + (size_t)(q0 + row) * QDIM + h * HDIM + ch * 8;
      CP_ASYNC16(sb + row * 144 + ch * 16, src);
    }
    load_stage(0, sb + ATT_ST);
    CP_COMMIT();
    CP_WAIT0();
  }
  __syncthreads();

  uint32_t qf[4][4];
#pragma unroll
  for (int s = 0; s < 4; s++) {
    uint32_t a = sb + (uint32_t)(w * 16 + (lane & 15)) * 144 + ((lane >> 4) << 4) + s * 32;
    LDMATRIX_X4(qf[s][0], qf[s][1], qf[s][2], qf[s][3], a);
  }

  float oacc[16][4];
#pragma unroll
  for (int n = 0; n < 16; n++)
#pragma unroll
    for (int c = 0; c < 4; c++) oacc[n][c] = 0.f;
  float m0r = -1e30f, m1r = -1e30f, l0r = 0.f, l1r = 0.f;
  const int rmin = q0 + w * 16;
  const int rmax = rmin + 15;
  const int r0g = rmin + (lane >> 2);
  const int r1g = r0g + 8;

  for (int kb = 0; kb < nk; kb++) {
    const int k0 = kb << 6;
    const uint32_t stg = sb + ATT_ST + (uint32_t)(kb & 1) * ATT_STGB;
    if (kb + 1 < nk) {
      load_stage((kb + 1) << 6, sb + ATT_ST + (uint32_t)((kb + 1) & 1) * ATT_STGB);
      CP_COMMIT();
    }

    if (k0 <= rmax) {
      float sacc[8][4];
#pragma unroll
      for (int j = 0; j < 8; j++)
#pragma unroll
        for (int c = 0; c < 4; c++) sacc[j][c] = 0.f;

#pragma unroll
      for (int j = 0; j < 8; j++) {
        uint32_t bh[2][4];
#pragma unroll
        for (int s2 = 0; s2 < 2; s2++) {
          uint32_t a = stg + (uint32_t)(j * 8 + (lane & 7)) * 144 + s2 * 64 + ((lane >> 3) & 3) * 16;
          LDMATRIX_X4(bh[s2][0], bh[s2][1], bh[s2][2], bh[s2][3], a);
        }
#pragma unroll
        for (int s = 0; s < 4; s++) {
          uint32_t b0 = bh[s >> 1][(s & 1) * 2], b1 = bh[s >> 1][(s & 1) * 2 + 1];
          MMA16816H(sacc[j][0], sacc[j][1], sacc[j][2], sacc[j][3],
                    qf[s][0], qf[s][1], qf[s][2], qf[s][3], b0, b1);
        }
      }

      const bool needmask = (k0 + 63) > rmin;
#pragma unroll
      for (int j = 0; j < 8; j++) {
        int cb = k0 + j * 8 + ((lane & 3) << 1);
        sacc[j][0] *= 0.125f; sacc[j][1] *= 0.125f;
        sacc[j][2] *= 0.125f; sacc[j][3] *= 0.125f;
        if (needmask) {
          if (cb     > r0g) sacc[j][0] = -1e30f;
          if (cb + 1 > r0g) sacc[j][1] = -1e30f;
          if (cb     > r1g) sacc[j][2] = -1e30f;
          if (cb + 1 > r1g) sacc[j][3] = -1e30f;
        }
      }

      float mx0 = -1e30f, mx1 = -1e30f;
#pragma unroll
      for (int j = 0; j < 8; j++) {
        mx0 = fmaxf(mx0, fmaxf(sacc[j][0], sacc[j][1]));
        mx1 = fmaxf(mx1, fmaxf(sacc[j][2], sacc[j][3]));
      }
      mx0 = fmaxf(mx0, __shfl_xor_sync(0xffffffffu, mx0, 1));
      mx0 = fmaxf(mx0, __shfl_xor_sync(0xffffffffu, mx0, 2));
      mx1 = fmaxf(mx1, __shfl_xor_sync(0xffffffffu, mx1, 1));
      mx1 = fmaxf(mx1, __shfl_xor_sync(0xffffffffu, mx1, 2));
      float mn0 = fmaxf(m0r, mx0), mn1 = fmaxf(m1r, mx1);
      float al0 = __expf(m0r - mn0), al1 = __expf(m1r - mn1);
      m0r = mn0; m1r = mn1;

      float sum0 = 0.f, sum1 = 0.f;
      uint32_t ph[8][2];
#pragma unroll
      for (int j = 0; j < 8; j++) {
        float p0 = __expf(sacc[j][0] - mn0);
        float p1 = __expf(sacc[j][1] - mn0);
        float p2 = __expf(sacc[j][2] - mn1);
        float p3 = __expf(sacc[j][3] - mn1);
        sum0 += p0 + p1; sum1 += p2 + p3;
        ph[j][0] = pack2h(p0, p1);
        ph[j][1] = pack2h(p2, p3);
      }
      sum0 += __shfl_xor_sync(0xffffffffu, sum0, 1);
      sum0 += __shfl_xor_sync(0xffffffffu, sum0, 2);
      sum1 += __shfl_xor_sync(0xffffffffu, sum1, 1);
      sum1 += __shfl_xor_sync(0xffffffffu, sum1, 2);
      l0r = l0r * al0 + sum0;
      l1r = l1r * al1 + sum1;
#pragma unroll
      for (int n = 0; n < 16; n++) {
        oacc[n][0] *= al0; oacc[n][1] *= al0;
        oacc[n][2] *= al1; oacc[n][3] *= al1;
      }

#pragma unroll
      for (int n = 0; n < 16; n++) {
        uint32_t vh[2][4];
#pragma unroll
        for (int s2 = 0; s2 < 2; s2++) {
          uint32_t a = stg + 9216 + (uint32_t)(n * 8 + (lane & 7)) * 144 + s2 * 64 + ((lane >> 3) & 3) * 16;
          LDMATRIX_X4(vh[s2][0], vh[s2][1], vh[s2][2], vh[s2][3], a);
        }
#pragma unroll
        for (int t = 0; t < 4; t++) {
          uint32_t a0 = ph[2 * t][0], a1 = ph[2 * t][1], a2 = ph[2 * t + 1][0], a3 = ph[2 * t + 1][1];
          uint32_t b0 = vh[t >> 1][(t & 1) * 2], b1 = vh[t >> 1][(t & 1) * 2 + 1];
          MMA16816H(oacc[n][0], oacc[n][1], oacc[n][2], oacc[n][3], a0, a1, a2, a3, b0, b1);
        }
      }
    }

    CP_WAIT0();
    __syncthreads();
  }

  float i0 = 1.f / l0r, i1 = 1.f / l1r;
#pragma unroll
  for (int n = 0; n < 16; n++) {
    int col = n * 8 + ((lane & 3) << 1);
    *(float2*)(O + ((size_t)h * S_LEN + r0g) * VD + col) = make_float2(oacc[n][0] * i0, oacc[n][1] * i0);
    *(float2*)(O + ((size_t)h * S_LEN + r1g) * VD + col) = make_float2(oacc[n][2] * i1, oacc[n][3] * i1);
  }
}

// ---------------- differential combine + RMS norm -> single fp16 ----------------
__global__ void combine_kernel(const float* __restrict__ O, __half* __restrict__ Ac16) {
  const int s = blockIdx.x;
  const int i = blockIdx.y;
  const int d = threadIdx.x;
  const float lam = g_lam;
  float o1 = O[((size_t)i * S_LEN + s) * VD + d];
  float o2 = O[((size_t)(i + 16) * S_LEN + s) * VD + d];
  float a = o1 - lam * o2;
  float ss = a * a;
#pragma unroll
  for (int off = 16; off > 0; off >>= 1)
    ss += __shfl_xor_sync(0xffffffffu, ss, off);
  __shared__ float ws[4];
  int warp = d >> 5, lane = d & 31;
  if (lane == 0) ws[warp] = ss;
  __syncthreads();
  float tot = ws[0] + ws[1] + ws[2] + ws[3];
  float r = rsqrtf(tot * (1.0f / 128.0f) + 1e-6f);
  float aval = (1.0f - LAMBDA_INIT) * a * r;
  Ac16[(size_t)s * QDIM + i * VD + d] = __float2half_rn(aval);
}

// ---------------- launch ----------------
extern "C" void kernel_launch(void* const* d_in, const int* in_sizes, int n_in,
                              void* d_out, int out_size) {
  const float* hidden = (const float*)d_in[0];
  const float* cosb   = (const float*)d_in[1];
  const float* sinb   = (const float*)d_in[2];
  const float* Wq     = (const float*)d_in[3];
  const float* Wk     = (const float*)d_in[4];
  const float* Wv     = (const float*)d_in[5];
  const float* Wo     = (const float*)d_in[6];
  const float* lq1    = (const float*)d_in[7];
  const float* lk1    = (const float*)d_in[8];
  const float* lq2    = (const float*)d_in[9];
  const float* lk2    = (const float*)d_in[10];
  float* out = (float*)d_out;

  float *Qp, *Kp, *Vp, *Op;
  cudaGetSymbolAddress((void**)&Qp, g_Q);
  cudaGetSymbolAddress((void**)&Kp, g_K);
  cudaGetSymbolAddress((void**)&Vp, g_V);
  cudaGetSymbolAddress((void**)&Op, g_O);
  __half *H16, *Wq16, *Wk16, *Wv16, *Wo16, *Ac16;
  cudaGetSymbolAddress((void**)&H16, g_H16);
  cudaGetSymbolAddress((void**)&Wq16, g_Wq16);
  cudaGetSymbolAddress((void**)&Wk16, g_Wk16);
  cudaGetSymbolAddress((void**)&Wv16, g_Wv16);
  cudaGetSymbolAddress((void**)&Wo16, g_Wo16);
  cudaGetSymbolAddress((void**)&Ac16, g_Ac16);
  __half *Q16p, *K16p, *Vt16p;
  cudaGetSymbolAddress((void**)&Q16p, g_Q16);
  cudaGetSymbolAddress((void**)&K16p, g_K16);
  cudaGetSymbolAddress((void**)&Vt16p, g_Vt16);

  cudaFuncSetAttribute(hgemm_qkv_kernel, cudaFuncAttributeMaxDynamicSharedMemorySize, GSMEM);
  cudaFuncSetAttribute(hgemm_o_kernel,   cudaFuncAttributeMaxDynamicSharedMemorySize, GSMEM);
  cudaFuncSetAttribute(flash_attn_hmma,  cudaFuncAttributeMaxDynamicSharedMemorySize, ATT_SMEM);

  // converts (fp32 -> fp16), device-side only
  {
    int n = S_LEN * HID;
    f2h_kernel<<<n / 4 / 256, 256>>>(hidden, H16, n);
    n = QDIM * HID;
    f2h_kernel<<<n / 4 / 256, 256>>>(Wq, Wq16, n);
    n = KVDIM * HID;
    f2h_kernel<<<n / 4 / 256, 256>>>(Wk, Wk16, n);
    f2h_kernel<<<n / 4 / 256, 256>>>(Wv, Wv16, n);
    n = HID * QDIM;
    f2h_kernel<<<n / 4 / 256, 256>>>(Wo, Wo16, n);
  }

  // lambda (independent)
  lam_kernel<<<1, 32>>>(lq1, lk1, lq2, lk2);

  // QKV projections (plain fp16, flat 384-CTA grid)
  hgemm_qkv_kernel<<<384, 256, GSMEM>>>(H16, Wq16, Wk16, Wv16, Qp, Kp, Vp);

  // RoPE -> fp16 (Q, K); V transpose -> fp16
  rope_h16_kernel<<<(S_LEN * (QDIM / 2)) / 256, 256>>>(Qp, cosb, sinb, Q16p, QDIM);
  rope_h16_kernel<<<(S_LEN * (KVDIM / 2)) / 256, 256>>>(Kp, cosb, sinb, K16p, KVDIM);
  vt16_kernel<<<dim3(KVDIM / 32, S_LEN / 32), dim3(32, 8)>>>(Vp, Vt16p);

  // attention (plain fp16 HMMA)
  flash_attn_hmma<<<dim3(16, NHEADS), 256, ATT_SMEM>>>(Q16p, K16p, Vt16p, Op);

  // combine + RMS norm -> fp16 A
  combine_kernel<<<dim3(S_LEN, 16), 128>>>(Op, Ac16);

  // output projection (plain fp16)
  hgemm_o_kernel<<<dim3(QDIM / 128, S_LEN / 128), 256, GSMEM>>>(Ac16, Wo16, out);
}

// round 15
// speedup vs baseline: 1.0433x; 1.0129x over previous
#include <cuda_runtime.h>
#include <cuda_fp16.h>
#include <math.h>
#include <stdint.h>

#define S_LEN 2048
#define HID   2048
#define NHEADS 32
#define HDIM   64
#define QDIM  2048
#define KVDIM  512
#define VD     128
#define LAMBDA_INIT 0.7455692280263552f

// ---------------- scratch ----------------
__device__ float g_Q[(size_t)S_LEN * QDIM];
__device__ float g_K[(size_t)S_LEN * KVDIM];
__device__ float g_V[(size_t)S_LEN * KVDIM];
__device__ float g_O[(size_t)NHEADS * S_LEN * VD];
__device__ float g_lam;
__device__ __align__(256) __half g_H16[(size_t)S_LEN * HID];
__device__ __align__(256) __half g_Wq16[(size_t)QDIM * HID];
__device__ __align__(256) __half g_Wk16[(size_t)KVDIM * HID];
__device__ __align__(256) __half g_Wv16[(size_t)KVDIM * HID];
__device__ __align__(256) __half g_Wo16[(size_t)HID * QDIM];
__device__ __align__(256) __half g_Ac16[(size_t)S_LEN * QDIM];
__device__ __align__(256) __half g_Q16[(size_t)S_LEN * QDIM];
__device__ __align__(256) __half g_K16[(size_t)S_LEN * KVDIM];
__device__ __align__(256) __half g_Vt16[(size_t)KVDIM * S_LEN];

// ---------------- helpers ----------------
__device__ __forceinline__ uint32_t smem_u32(const void* p) {
  uint32_t r;
  asm("{ .reg .u64 t; cvta.to.shared.u64 t, %1; cvt.u32.u64 %0, t; }" : "=r"(r) : "l"(p));
  return r;
}
#define CP_ASYNC16(sa, ga) \
  asm volatile("cp.async.cg.shared.global [%0], [%1], 16;" :: "r"(sa), "l"(ga) : "memory")
#define CP_COMMIT() asm volatile("cp.async.commit_group;" ::: "memory")
#define CP_WAIT0()  asm volatile("cp.async.wait_group 0;" ::: "memory")

#define LDMATRIX_X4(r0, r1, r2, r3, addr) \
  asm volatile("ldmatrix.sync.aligned.m8n8.x4.shared.b16 {%0,%1,%2,%3}, [%4];" \
               : "=r"(r0), "=r"(r1), "=r"(r2), "=r"(r3) : "r"(addr))

#define MMA16816H(c0, c1, c2, c3, a0, a1, a2, a3, b0, b1) \
  asm volatile("mma.sync.aligned.m16n8k16.row.col.f32.f16.f16.f32 " \
               "{%0,%1,%2,%3}, {%4,%5,%6,%7}, {%8,%9}, {%0,%1,%2,%3};" \
               : "+f"(c0), "+f"(c1), "+f"(c2), "+f"(c3) \
               : "r"(a0), "r"(a1), "r"(a2), "r"(a3), "r"(b0), "r"(b1))

__device__ __forceinline__ uint32_t pack2h(float a, float b) {
  __half2 h = __floats2half2_rn(a, b);
  return *(uint32_t*)&h;
}

// ---------------- fp16 HMMA GEMM: C[M,N] = A[M,Kc] @ B[N,Kc]^T ----------------
#define GROWB 144
#define GTILE (128 * GROWB)
#define GSTAGE (2 * GTILE)
#define GSMEM (2 * GSTAGE)

__device__ __forceinline__ void hgemm_core(
    const __half* __restrict__ A, const __half* __restrict__ B,
    float* __restrict__ C, int N, int Kc, int m0, int n0, char* sm) {
  const int tid = threadIdx.x;
  const int warp = tid >> 5;
  const int lane = tid & 31;
  const int wm = warp & 1;
  const int wn = warp >> 1;
  const uint32_t sb = smem_u32(sm);

  const int lrow = tid >> 1;
  const int lch0 = (tid & 1) << 2;

  float acc[4][4][4];
#pragma unroll
  for (int i = 0; i < 4; i++)
#pragma unroll
    for (int j = 0; j < 4; j++)
#pragma unroll
      for (int c = 0; c < 4; c++) acc[i][j][c] = 0.f;

  const int nT = Kc >> 6;

  auto load_stage = [&](int k0, uint32_t st) {
    const __half* ag = A + (size_t)(m0 + lrow) * Kc + k0 + lch0 * 8;
    const __half* bg = B + (size_t)(n0 + lrow) * Kc + k0 + lch0 * 8;
    uint32_t so = st + lrow * GROWB + lch0 * 16;
#pragma unroll
    for (int c = 0; c < 4; c++) {
      CP_ASYNC16(so + c * 16, ag + c * 8);
      CP_ASYNC16(so + GTILE + c * 16, bg + c * 8);
    }
  };

  load_stage(0, sb);
  CP_COMMIT();

  for (int t = 0; t < nT; ++t) {
    CP_WAIT0();
    __syncthreads();
    const uint32_t cur = sb + (uint32_t)(t & 1) * GSTAGE;
    if (t + 1 < nT) {
      load_stage((t + 1) << 6, sb + (uint32_t)((t + 1) & 1) * GSTAGE);
      CP_COMMIT();
    }

#pragma unroll
    for (int ks = 0; ks < 4; ++ks) {
      uint32_t a[4][4];
#pragma unroll
      for (int mi = 0; mi < 4; ++mi) {
        uint32_t addr = cur + (uint32_t)((wm << 6) + (mi << 4) + (lane & 15)) * GROWB
                        + ((lane >> 4) << 4) + (ks << 5);
        LDMATRIX_X4(a[mi][0], a[mi][1], a[mi][2], a[mi][3], addr);
      }
      uint32_t b[4][2];
#pragma unroll
      for (int pr = 0; pr < 2; ++pr) {
        int r = (lane & 7) + (((lane >> 4) & 1) << 3);
        int hk = (lane >> 3) & 1;
        uint32_t addr = cur + GTILE + (uint32_t)((wn << 5) + (pr << 4) + r) * GROWB
                        + (hk << 4) + (ks << 5);
        uint32_t r0, r1, r2, r3;
        LDMATRIX_X4(r0, r1, r2, r3, addr);
        b[pr * 2 + 0][0] = r0; b[pr * 2 + 0][1] = r1;
        b[pr * 2 + 1][0] = r2; b[pr * 2 + 1][1] = r3;
      }
#pragma unroll
      for (int mi = 0; mi < 4; ++mi)
#pragma unroll
        for (int ni = 0; ni < 4; ++ni)
          MMA16816H(acc[mi][ni][0], acc[mi][ni][1], acc[mi][ni][2], acc[mi][ni][3],
                    a[mi][0], a[mi][1], a[mi][2], a[mi][3], b[ni][0], b[ni][1]);
    }
  }

#pragma unroll
  for (int mi = 0; mi < 4; ++mi) {
    int row = m0 + (wm << 6) + (mi << 4) + (lane >> 2);
#pragma unroll
    for (int ni = 0; ni < 4; ++ni) {
      int col = n0 + (wn << 5) + (ni << 3) + ((lane & 3) << 1);
      *(float2*)(C + (size_t)row * N + col)       = make_float2(acc[mi][ni][0], acc[mi][ni][1]);
      *(float2*)(C + (size_t)(row + 8) * N + col) = make_float2(acc[mi][ni][2], acc[mi][ni][3]);
    }
  }
}

// flat 384-CTA QKV grid: [0,256) Q, [256,320) K, [320,384) V
__global__ __launch_bounds__(256, 2) void hgemm_qkv_kernel(
    const __half* __restrict__ H16,
    const __half* __restrict__ Wq16, const __half* __restrict__ Wk16,
    const __half* __restrict__ Wv16,
    float* __restrict__ Qo, float* __restrict__ Ko, float* __restrict__ Vo) {
  extern __shared__ char sm[];
  const int bid = blockIdx.x;
  const __half* Bp;
  float* C;
  int N, n0, m0;
  if (bid < 256)      { Bp = Wq16; C = Qo; N = QDIM;  n0 = (bid & 15) << 7;        m0 = (bid >> 4) << 7; }
  else if (bid < 320) { int u = bid - 256; Bp = Wk16; C = Ko; N = KVDIM; n0 = (u & 3) << 7; m0 = (u >> 2) << 7; }
  else                { int u = bid - 320; Bp = Wv16; C = Vo; N = KVDIM; n0 = (u & 3) << 7; m0 = (u >> 2) << 7; }
  hgemm_core(H16, Bp, C, N, HID, m0, n0, sm);
}

__global__ __launch_bounds__(256, 2) void hgemm_o_kernel(
    const __half* __restrict__ Ac16, const __half* __restrict__ Wo16,
    float* __restrict__ out) {
  extern __shared__ char sm[];
  hgemm_core(Ac16, Wo16, out, HID, QDIM, blockIdx.y << 7, blockIdx.x << 7, sm);
}

// ---------------- batched fp32 -> fp16 convert (pointers as args: capture-safe) ----------------
#define N4_H  ((S_LEN * HID) / 4)
#define N4_WQ ((QDIM * HID) / 4)
#define N4_WK ((KVDIM * HID) / 4)
#define N4_WV ((KVDIM * HID) / 4)
#define N4_WO ((HID * QDIM) / 4)
#define OFF1 (N4_H)
#define OFF2 (OFF1 + N4_WQ)
#define OFF3 (OFF2 + N4_WK)
#define OFF4 (OFF3 + N4_WV)
#define OFF5 (OFF4 + N4_WO)

__global__ void f2h_all_kernel(
    const float* __restrict__ s0, const float* __restrict__ s1,
    const float* __restrict__ s2, const float* __restrict__ s3,
    const float* __restrict__ s4,
    __half* __restrict__ d0, __half* __restrict__ d1,
    __half* __restrict__ d2, __half* __restrict__ d3,
    __half* __restrict__ d4) {
  int i = blockIdx.x * blockDim.x + threadIdx.x;
  if (i >= OFF5) return;
  const float* src;
  __half* dst;
  int li;
  if (i < OFF1)      { src = s0; dst = d0; li = i; }
  else if (i < OFF2) { src = s1; dst = d1; li = i - OFF1; }
  else if (i < OFF3) { src = s2; dst = d2; li = i - OFF2; }
  else if (i < OFF4) { src = s3; dst = d3; li = i - OFF3; }
  else               { src = s4; dst = d4; li = i - OFF4; }
  float4 v = *((const float4*)src + li);
  uint2 ph;
  ph.x = (uint32_t)__half_as_ushort(__float2half_rn(v.x)) |
         ((uint32_t)__half_as_ushort(__float2half_rn(v.y)) << 16);
  ph.y = (uint32_t)__half_as_ushort(__float2half_rn(v.z)) |
         ((uint32_t)__half_as_ushort(__float2half_rn(v.w)) << 16);
  *((uint2*)dst + li) = ph;
}

// ---------------- RoPE Q+K -> single fp16 (one launch) ----------------
#define QPAIRS (S_LEN * (QDIM / 2))
#define KPAIRS (S_LEN * (KVDIM / 2))

__global__ void rope_all_kernel(const float* __restrict__ Qf, const float* __restrict__ Kf,
                                const float* __restrict__ cosb, const float* __restrict__ sinb,
                                __half* __restrict__ Q16, __half* __restrict__ K16) {
  int idx = blockIdx.x * blockDim.x + threadIdx.x;
  const float* X;
  __half* X16;
  int width, pairsPerRow;
  if (idx < QPAIRS) { X = Qf; X16 = Q16; width = QDIM; pairsPerRow = QDIM >> 1; }
  else {
    idx -= QPAIRS;
    if (idx >= KPAIRS) return;
    X = Kf; X16 = K16; width = KVDIM; pairsPerRow = KVDIM >> 1;
  }
  int s = idx / pairsPerRow;
  int p = idx - s * pairsPerRow;
  int head = p >> 5;
  int d = p & 31;
  int c1 = head * HDIM + d;
  float c   = cosb[s * HDIM + d];
  float sn  = sinb[s * HDIM + d];
  float c2  = cosb[s * HDIM + d + 32];
  float sn2 = sinb[s * HDIM + d + 32];
  size_t base = (size_t)s * width;
  float x1 = X[base + c1];
  float x2 = X[base + c1 + 32];
  X16[base + c1]      = __float2half_rn(x1 * c  - x2 * sn);
  X16[base + c1 + 32] = __float2half_rn(x2 * c2 + x1 * sn2);
}

// ---------------- V transpose -> single fp16: Vt[d][s] ----------------
__global__ void vt16_kernel(const float* __restrict__ V, __half* __restrict__ Vt16) {
  __shared__ float tile[32][33];
  int c0 = blockIdx.x << 5;
  int s0 = blockIdx.y << 5;
  int tx = threadIdx.x, ty = threadIdx.y;
#pragma unroll
  for (int i = 0; i < 4; i++)
    tile[ty + i * 8][tx] = V[(size_t)(s0 + ty + i * 8) * KVDIM + c0 + tx];
  __syncthreads();
#pragma unroll
  for (int i = 0; i < 4; i++) {
    int r = ty + i * 8;
    Vt16[(size_t)(c0 + r) * S_LEN + s0 + tx] = __float2half_rn(tile[tx][r]);
  }
}

// ---------------- lambda ----------------
__global__ void lam_kernel(const float* __restrict__ lq1, const float* __restrict__ lk1,
                           const float* __restrict__ lq2, const float* __restrict__ lk2) {
  int d = threadIdx.x;
  float s1 = lq1[d] * lk1[d] + lq1[d + 32] * lk1[d + 32];
  float s2 = lq2[d] * lk2[d] + lq2[d + 32] * lk2[d + 32];
#pragma unroll
  for (int off = 16; off > 0; off >>= 1) {
    s1 += __shfl_xor_sync(0xffffffffu, s1, off);
    s2 += __shfl_xor_sync(0xffffffffu, s2, off);
  }
  if (d == 0) g_lam = expf(s1) - expf(s2) + LAMBDA_INIT;
}

// ---------------- HMMA flash attention: plain fp16 ----------------
#define ATT_ST   18432
#define ATT_STGB 27648
#define ATT_SMEM (18432 + 2 * 27648)    // 73728

__global__ __launch_bounds__(256, 2) void flash_attn_hmma(
    const __half* __restrict__ Q16, const __half* __restrict__ K16,
    const __half* __restrict__ Vt16, float* __restrict__ O) {
  extern __shared__ char sm[];
  const uint32_t sb = smem_u32(sm);
  const int tid = threadIdx.x;
  const int w = tid >> 5, lane = tid & 31;
  const int h = blockIdx.y;
  const int qb = 15 - (int)blockIdx.x;
  const int q0 = qb << 7;
  const int kh = h >> 2;
  const int ii = h & 15;
  const int vh0 = ii >> 2, vh1 = 4 + (ii >> 2);
  const int nk = 2 * qb + 2;

  auto load_stage = [&](int k0, uint32_t stg) {
#pragma unroll
    for (int i = 0; i < 6; i++) {
      int id = tid + (i << 8);
      if (id < 512) {
        int row = id >> 3, ch = id & 7;
        const __half* src = K16 + (size_t)(k0 + row) * KVDIM + kh * HDIM + ch * 8;
        CP_ASYNC16(stg + row * 144 + ch * 16, src);
      } else {
        int t = id - 512;
        int row = t >> 3, ch = t & 7;
        int grow = (row < 64) ? (vh0 * HDIM + row) : (vh1 * HDIM + row - 64);
        const __half* src = Vt16 + (size_t)grow * S_LEN + k0 + ch * 8;
        CP_ASYNC16(stg + 9216 + row * 144 + ch * 16, src);
      }
    }
  };

  {
#pragma unroll
    for (int i = 0; i < 4; i++) {
      int id = tid + (i << 8);
      int row = id >> 3, ch = id & 7;
      const __half* src = Q16 + (size_t)(q0 + row) * QDIM + h * HDIM + ch * 8;
      CP_ASYNC16(sb + row * 144 + ch * 16, src);
    }
    load_stage(0, sb + ATT_ST);
    CP_COMMIT();
    CP_WAIT0();
  }
  __syncthreads();

  uint32_t qf[4][4];
#pragma unroll
  for (int s = 0; s < 4; s++) {
    uint32_t a = sb + (uint32_t)(w * 16 + (lane & 15)) * 144 + ((lane >> 4) << 4) + s * 32;
    LDMATRIX_X4(qf[s][0], qf[s][1], qf[s][2], qf[s][3], a);
  }

  float oacc[16][4];
#pragma unroll
  for (int n = 0; n < 16; n++)
#pragma unroll
    for (int c = 0; c < 4; c++) oacc[n][c] = 0.f;
  float m0r = -1e30f, m1r = -1e30f, l0r = 0.f, l1r = 0.f;
  const int rmin = q0 + w * 16;
  const int rmax = rmin + 15;
  const int r0g = rmin + (lane >> 2);
  const int r1g = r0g + 8;

  for (int kb = 0; kb < nk; kb++) {
    const int k0 = kb << 6;
    const uint32_t stg = sb + ATT_ST + (uint32_t)(kb & 1) * ATT_STGB;
    if (kb + 1 < nk) {
      load_stage((kb + 1) << 6, sb + ATT_ST + (uint32_t)((kb + 1) & 1) * ATT_STGB);
      CP_COMMIT();
    }

    if (k0 <= rmax) {
      float sacc[8][4];
#pragma unroll
      for (int j = 0; j < 8; j++)
#pragma unroll
        for (int c = 0; c < 4; c++) sacc[j][c] = 0.f;

#pragma unroll
      for (int j = 0; j < 8; j++) {
        uint32_t bh[2][4];
#pragma unroll
        for (int s2 = 0; s2 < 2; s2++) {
          uint32_t a = stg + (uint32_t)(j * 8 + (lane & 7)) * 144 + s2 * 64 + ((lane >> 3) & 3) * 16;
          LDMATRIX_X4(bh[s2][0], bh[s2][1], bh[s2][2], bh[s2][3], a);
        }
#pragma unroll
        for (int s = 0; s < 4; s++) {
          uint32_t b0 = bh[s >> 1][(s & 1) * 2], b1 = bh[s >> 1][(s & 1) * 2 + 1];
          MMA16816H(sacc[j][0], sacc[j][1], sacc[j][2], sacc[j][3],
                    qf[s][0], qf[s][1], qf[s][2], qf[s][3], b0, b1);
        }
      }

      const bool needmask = (k0 + 63) > rmin;
#pragma unroll
      for (int j = 0; j < 8; j++) {
        int cb = k0 + j * 8 + ((lane & 3) << 1);
        sacc[j][0] *= 0.125f; sacc[j][1] *= 0.125f;
        sacc[j][2] *= 0.125f; sacc[j][3] *= 0.125f;
        if (needmask) {
          if (cb     > r0g) sacc[j][0] = -1e30f;
          if (cb + 1 > r0g) sacc[j][1] = -1e30f;
          if (cb     > r1g) sacc[j][2] = -1e30f;
          if (cb + 1 > r1g) sacc[j][3] = -1e30f;
        }
      }

      float mx0 = -1e30f, mx1 = -1e30f;
#pragma unroll
      for (int j = 0; j < 8; j++) {
        mx0 = fmaxf(mx0, fmaxf(sacc[j][0], sacc[j][1]));
        mx1 = fmaxf(mx1, fmaxf(sacc[j][2], sacc[j][3]));
      }
      mx0 = fmaxf(mx0, __shfl_xor_sync(0xffffffffu, mx0, 1));
      mx0 = fmaxf(mx0, __shfl_xor_sync(0xffffffffu, mx0, 2));
      mx1 = fmaxf(mx1, __shfl_xor_sync(0xffffffffu, mx1, 1));
      mx1 = fmaxf(mx1, __shfl_xor_sync(0xffffffffu, mx1, 2));
      float mn0 = fmaxf(m0r, mx0), mn1 = fmaxf(m1r, mx1);
      float al0 = __expf(m0r - mn0), al1 = __expf(m1r - mn1);
      m0r = mn0; m1r = mn1;

      float sum0 = 0.f, sum1 = 0.f;
      uint32_t ph[8][2];
#pragma unroll
      for (int j = 0; j < 8; j++) {
        float p0 = __expf(sacc[j][0] - mn0);
        float p1 = __expf(sacc[j][1] - mn0);
        float p2 = __expf(sacc[j][2] - mn1);
        float p3 = __expf(sacc[j][3] - mn1);
        sum0 += p0 + p1; sum1 += p2 + p3;
        ph[j][0] = pack2h(p0, p1);
        ph[j][1] = pack2h(p2, p3);
      }
      sum0 += __shfl_xor_sync(0xffffffffu, sum0, 1);
      sum0 += __shfl_xor_sync(0xffffffffu, sum0, 2);
      sum1 += __shfl_xor_sync(0xffffffffu, sum1, 1);
      sum1 += __shfl_xor_sync(0xffffffffu, sum1, 2);
      l0r = l0r * al0 + sum0;
      l1r = l1r * al1 + sum1;
#pragma unroll
      for (int n = 0; n < 16; n++) {
        oacc[n][0] *= al0; oacc[n][1] *= al0;
        oacc[n][2] *= al1; oacc[n][3] *= al1;
      }

#pragma unroll
      for (int n = 0; n < 16; n++) {
        uint32_t vh[2][4];
#pragma unroll
        for (int s2 = 0; s2 < 2; s2++) {
          uint32_t a = stg + 9216 + (uint32_t)(n * 8 + (lane & 7)) * 144 + s2 * 64 + ((lane >> 3) & 3) * 16;
          LDMATRIX_X4(vh[s2][0], vh[s2][1], vh[s2][2], vh[s2][3], a);
        }
#pragma unroll
        for (int t = 0; t < 4; t++) {
          uint32_t a0 = ph[2 * t][0], a1 = ph[2 * t][1], a2 = ph[2 * t + 1][0], a3 = ph[2 * t + 1][1];
          uint32_t b0 = vh[t >> 1][(t & 1) * 2], b1 = vh[t >> 1][(t & 1) * 2 + 1];
          MMA16816H(oacc[n][0], oacc[n][1], oacc[n][2], oacc[n][3], a0, a1, a2, a3, b0, b1);
        }
      }
    }

    CP_WAIT0();
    __syncthreads();
  }

  float i0 = 1.f / l0r, i1 = 1.f / l1r;
#pragma unroll
  for (int n = 0; n < 16; n++) {
    int col = n * 8 + ((lane & 3) << 1);
    *(float2*)(O + ((size_t)h * S_LEN + r0g) * VD + col) = make_float2(oacc[n][0] * i0, oacc[n][1] * i0);
    *(float2*)(O + ((size_t)h * S_LEN + r1g) * VD + col) = make_float2(oacc[n][2] * i1, oacc[n][3] * i1);
  }
}

// ---------------- differential combine + RMS norm -> single fp16 ----------------
__global__ void combine_kernel(const float* __restrict__ O, __half* __restrict__ Ac16) {
  const int s = blockIdx.x;
  const int i = blockIdx.y;
  const int d = threadIdx.x;
  const float lam = g_lam;
  float o1 = O[((size_t)i * S_LEN + s) * VD + d];
  float o2 = O[((size_t)(i + 16) * S_LEN + s) * VD + d];
  float a = o1 - lam * o2;
  float ss = a * a;
#pragma unroll
  for (int off = 16; off > 0; off >>= 1)
    ss += __shfl_xor_sync(0xffffffffu, ss, off);
  __shared__ float ws[4];
  int warp = d >> 5, lane = d & 31;
  if (lane == 0) ws[warp] = ss;
  __syncthreads();
  float tot = ws[0] + ws[1] + ws[2] + ws[3];
  float r = rsqrtf(tot * (1.0f / 128.0f) + 1e-6f);
  float aval = (1.0f - LAMBDA_INIT) * a * r;
  Ac16[(size_t)s * QDIM + i * VD + d] = __float2half_rn(aval);
}

// ---------------- launch ----------------
extern "C" void kernel_launch(void* const* d_in, const int* in_sizes, int n_in,
                              void* d_out, int out_size) {
  const float* hidden = (const float*)d_in[0];
  const float* cosb   = (const float*)d_in[1];
  const float* sinb   = (const float*)d_in[2];
  const float* Wq     = (const float*)d_in[3];
  const float* Wk     = (const float*)d_in[4];
  const float* Wv     = (const float*)d_in[5];
  const float* Wo     = (const float*)d_in[6];
  const float* lq1    = (const float*)d_in[7];
  const float* lk1    = (const float*)d_in[8];
  const float* lq2    = (const float*)d_in[9];
  const float* lk2    = (const float*)d_in[10];
  float* out = (float*)d_out;

  float *Qp, *Kp, *Vp, *Op;
  cudaGetSymbolAddress((void**)&Qp, g_Q);
  cudaGetSymbolAddress((void**)&Kp, g_K);
  cudaGetSymbolAddress((void**)&Vp, g_V);
  cudaGetSymbolAddress((void**)&Op, g_O);
  __half *H16, *Wq16, *Wk16, *Wv16, *Wo16, *Ac16;
  cudaGetSymbolAddress((void**)&H16, g_H16);
  cudaGetSymbolAddress((void**)&Wq16, g_Wq16);
  cudaGetSymbolAddress((void**)&Wk16, g_Wk16);
  cudaGetSymbolAddress((void**)&Wv16, g_Wv16);
  cudaGetSymbolAddress((void**)&Wo16, g_Wo16);
  cudaGetSymbolAddress((void**)&Ac16, g_Ac16);
  __half *Q16p, *K16p, *Vt16p;
  cudaGetSymbolAddress((void**)&Q16p, g_Q16);
  cudaGetSymbolAddress((void**)&K16p, g_K16);
  cudaGetSymbolAddress((void**)&Vt16p, g_Vt16);

  cudaFuncSetAttribute(hgemm_qkv_kernel, cudaFuncAttributeMaxDynamicSharedMemorySize, GSMEM);
  cudaFuncSetAttribute(hgemm_o_kernel,   cudaFuncAttributeMaxDynamicSharedMemorySize, GSMEM);
  cudaFuncSetAttribute(flash_attn_hmma,  cudaFuncAttributeMaxDynamicSharedMemorySize, ATT_SMEM);

  // single batched convert (all pointers passed as kernel args: capture-safe)
  f2h_all_kernel<<<(OFF5 + 255) / 256, 256>>>(hidden, Wq, Wk, Wv, Wo,
                                              H16, Wq16, Wk16, Wv16, Wo16);

  // lambda (independent)
  lam_kernel<<<1, 32>>>(lq1, lk1, lq2, lk2);

  // QKV projections (plain fp16, flat 384-CTA grid)
  hgemm_qkv_kernel<<<384, 256, GSMEM>>>(H16, Wq16, Wk16, Wv16, Qp, Kp, Vp);

  // RoPE Q+K in one launch; V transpose
  rope_all_kernel<<<(QPAIRS + KPAIRS + 255) / 256, 256>>>(Qp, Kp, cosb, sinb, Q16p, K16p);
  vt16_kernel<<<dim3(KVDIM / 32, S_LEN / 32), dim3(32, 8)>>>(Vp, Vt16p);

  // attention (plain fp16 HMMA)
  flash_attn_hmma<<<dim3(16, NHEADS), 256, ATT_SMEM>>>(Q16p, K16p, Vt16p, Op);

  // combine + RMS norm -> fp16 A
  combine_kernel<<<dim3(S_LEN, 16), 128>>>(Op, Ac16);

  // output projection (plain fp16)
  hgemm_o_kernel<<<dim3(QDIM / 128, S_LEN / 128), 256, GSMEM>>>(Ac16, Wo16, out);
}

// round 16
// speedup vs baseline: 1.0859x; 1.0409x over previous
#include <cuda_runtime.h>
#include <cuda_fp16.h>
#include <math.h>
#include <stdint.h>

#define S_LEN 2048
#define HID   2048
#define NHEADS 32
#define HDIM   64
#define QDIM  2048
#define KVDIM  512
#define VD     128
#define LAMBDA_INIT 0.7455692280263552f

// ---------------- scratch ----------------
__device__ float g_Q[(size_t)S_LEN * QDIM];
__device__ float g_K[(size_t)S_LEN * KVDIM];
__device__ float g_V[(size_t)S_LEN * KVDIM];
__device__ float g_O[(size_t)NHEADS * S_LEN * VD];
__device__ float g_lam;
__device__ __align__(256) __half g_H16[(size_t)S_LEN * HID];
__device__ __align__(256) __half g_Wq16[(size_t)QDIM * HID];
__device__ __align__(256) __half g_Wk16[(size_t)KVDIM * HID];
__device__ __align__(256) __half g_Wv16[(size_t)KVDIM * HID];
__device__ __align__(256) __half g_Wo16[(size_t)HID * QDIM];
__device__ __align__(256) __half g_Ac16[(size_t)S_LEN * QDIM];
__device__ __align__(256) __half g_Q16[(size_t)S_LEN * QDIM];
__device__ __align__(256) __half g_K16[(size_t)S_LEN * KVDIM];
__device__ __align__(256) __half g_Vt16[(size_t)KVDIM * S_LEN];

// ---------------- helpers ----------------
__device__ __forceinline__ uint32_t smem_u32(const void* p) {
  uint32_t r;
  asm("{ .reg .u64 t; cvta.to.shared.u64 t, %1; cvt.u32.u64 %0, t; }" : "=r"(r) : "l"(p));
  return r;
}
#define CP_ASYNC16(sa, ga) \
  asm volatile("cp.async.cg.shared.global [%0], [%1], 16;" :: "r"(sa), "l"(ga) : "memory")
#define CP_COMMIT() asm volatile("cp.async.commit_group;" ::: "memory")
#define CP_WAIT0()  asm volatile("cp.async.wait_group 0;" ::: "memory")

#define LDMATRIX_X4(r0, r1, r2, r3, addr) \
  asm volatile("ldmatrix.sync.aligned.m8n8.x4.shared.b16 {%0,%1,%2,%3}, [%4];" \
               : "=r"(r0), "=r"(r1), "=r"(r2), "=r"(r3) : "r"(addr))

#define MMA16816H(c0, c1, c2, c3, a0, a1, a2, a3, b0, b1) \
  asm volatile("mma.sync.aligned.m16n8k16.row.col.f32.f16.f16.f32 " \
               "{%0,%1,%2,%3}, {%4,%5,%6,%7}, {%8,%9}, {%0,%1,%2,%3};" \
               : "+f"(c0), "+f"(c1), "+f"(c2), "+f"(c3) \
               : "r"(a0), "r"(a1), "r"(a2), "r"(a3), "r"(b0), "r"(b1))

__device__ __forceinline__ uint32_t pack2h(float a, float b) {
  __half2 h = __floats2half2_rn(a, b);
  return *(uint32_t*)&h;
}

// ---------------- fp16 HMMA GEMM: C[M,N] = A[M,Kc] @ B[N,Kc]^T ----------------
#define GROWB 144
#define GTILE (128 * GROWB)
#define GSTAGE (2 * GTILE)
#define GSMEM (2 * GSTAGE)

__device__ __forceinline__ void hgemm_core(
    const __half* __restrict__ A, const __half* __restrict__ B,
    float* __restrict__ C, int N, int Kc, int m0, int n0, char* sm) {
  const int tid = threadIdx.x;
  const int warp = tid >> 5;
  const int lane = tid & 31;
  const int wm = warp & 1;
  const int wn = warp >> 1;
  const uint32_t sb = smem_u32(sm);

  const int lrow = tid >> 1;
  const int lch0 = (tid & 1) << 2;

  float acc[4][4][4];
#pragma unroll
  for (int i = 0; i < 4; i++)
#pragma unroll
    for (int j = 0; j < 4; j++)
#pragma unroll
      for (int c = 0; c < 4; c++) acc[i][j][c] = 0.f;

  const int nT = Kc >> 6;

  auto load_stage = [&](int k0, uint32_t st) {
    const __half* ag = A + (size_t)(m0 + lrow) * Kc + k0 + lch0 * 8;
    const __half* bg = B + (size_t)(n0 + lrow) * Kc + k0 + lch0 * 8;
    uint32_t so = st + lrow * GROWB + lch0 * 16;
#pragma unroll
    for (int c = 0; c < 4; c++) {
      CP_ASYNC16(so + c * 16, ag + c * 8);
      CP_ASYNC16(so + GTILE + c * 16, bg + c * 8);
    }
  };

  load_stage(0, sb);
  CP_COMMIT();

  for (int t = 0; t < nT; ++t) {
    CP_WAIT0();
    __syncthreads();
    const uint32_t cur = sb + (uint32_t)(t & 1) * GSTAGE;
    if (t + 1 < nT) {
      load_stage((t + 1) << 6, sb + (uint32_t)((t + 1) & 1) * GSTAGE);
      CP_COMMIT();
    }

#pragma unroll
    for (int ks = 0; ks < 4; ++ks) {
      uint32_t a[4][4];
#pragma unroll
      for (int mi = 0; mi < 4; ++mi) {
        uint32_t addr = cur + (uint32_t)((wm << 6) + (mi << 4) + (lane & 15)) * GROWB
                        + ((lane >> 4) << 4) + (ks << 5);
        LDMATRIX_X4(a[mi][0], a[mi][1], a[mi][2], a[mi][3], addr);
      }
      uint32_t b[4][2];
#pragma unroll
      for (int pr = 0; pr < 2; ++pr) {
        int r = (lane & 7) + (((lane >> 4) & 1) << 3);
        int hk = (lane >> 3) & 1;
        uint32_t addr = cur + GTILE + (uint32_t)((wn << 5) + (pr << 4) + r) * GROWB
                        + (hk << 4) + (ks << 5);
        uint32_t r0, r1, r2, r3;
        LDMATRIX_X4(r0, r1, r2, r3, addr);
        b[pr * 2 + 0][0] = r0; b[pr * 2 + 0][1] = r1;
        b[pr * 2 + 1][0] = r2; b[pr * 2 + 1][1] = r3;
      }
#pragma unroll
      for (int mi = 0; mi < 4; ++mi)
#pragma unroll
        for (int ni = 0; ni < 4; ++ni)
          MMA16816H(acc[mi][ni][0], acc[mi][ni][1], acc[mi][ni][2], acc[mi][ni][3],
                    a[mi][0], a[mi][1], a[mi][2], a[mi][3], b[ni][0], b[ni][1]);
    }
  }

#pragma unroll
  for (int mi = 0; mi < 4; ++mi) {
    int row = m0 + (wm << 6) + (mi << 4) + (lane >> 2);
#pragma unroll
    for (int ni = 0; ni < 4; ++ni) {
      int col = n0 + (wn << 5) + (ni << 3) + ((lane & 3) << 1);
      *(float2*)(C + (size_t)row * N + col)       = make_float2(acc[mi][ni][0], acc[mi][ni][1]);
      *(float2*)(C + (size_t)(row + 8) * N + col) = make_float2(acc[mi][ni][2], acc[mi][ni][3]);
    }
  }
}

// flat 384-CTA QKV grid: [0,256) Q, [256,320) K, [320,384) V
__global__ __launch_bounds__(256, 2) void hgemm_qkv_kernel(
    const __half* __restrict__ H16,
    const __half* __restrict__ Wq16, const __half* __restrict__ Wk16,
    const __half* __restrict__ Wv16,
    float* __restrict__ Qo, float* __restrict__ Ko, float* __restrict__ Vo) {
  extern __shared__ char sm[];
  const int bid = blockIdx.x;
  const __half* Bp;
  float* C;
  int N, n0, m0;
  if (bid < 256)      { Bp = Wq16; C = Qo; N = QDIM;  n0 = (bid & 15) << 7;        m0 = (bid >> 4) << 7; }
  else if (bid < 320) { int u = bid - 256; Bp = Wk16; C = Ko; N = KVDIM; n0 = (u & 3) << 7; m0 = (u >> 2) << 7; }
  else                { int u = bid - 320; Bp = Wv16; C = Vo; N = KVDIM; n0 = (u & 3) << 7; m0 = (u >> 2) << 7; }
  hgemm_core(H16, Bp, C, N, HID, m0, n0, sm);
}

__global__ __launch_bounds__(256, 2) void hgemm_o_kernel(
    const __half* __restrict__ Ac16, const __half* __restrict__ Wo16,
    float* __restrict__ out) {
  extern __shared__ char sm[];
  hgemm_core(Ac16, Wo16, out, HID, QDIM, blockIdx.y << 7, blockIdx.x << 7, sm);
}

// ---------------- batched fp32 -> fp16 convert ----------------
#define N4_H  ((S_LEN * HID) / 4)
#define N4_WQ ((QDIM * HID) / 4)
#define N4_WK ((KVDIM * HID) / 4)
#define N4_WV ((KVDIM * HID) / 4)
#define N4_WO ((HID * QDIM) / 4)
#define OFF1 (N4_H)
#define OFF2 (OFF1 + N4_WQ)
#define OFF3 (OFF2 + N4_WK)
#define OFF4 (OFF3 + N4_WV)
#define OFF5 (OFF4 + N4_WO)

__global__ void f2h_all_kernel(
    const float* __restrict__ s0, const float* __restrict__ s1,
    const float* __restrict__ s2, const float* __restrict__ s3,
    const float* __restrict__ s4,
    __half* __restrict__ d0, __half* __restrict__ d1,
    __half* __restrict__ d2, __half* __restrict__ d3,
    __half* __restrict__ d4) {
  int i = blockIdx.x * blockDim.x + threadIdx.x;
  if (i >= OFF5) return;
  const float* src;
  __half* dst;
  int li;
  if (i < OFF1)      { src = s0; dst = d0; li = i; }
  else if (i < OFF2) { src = s1; dst = d1; li = i - OFF1; }
  else if (i < OFF3) { src = s2; dst = d2; li = i - OFF2; }
  else if (i < OFF4) { src = s3; dst = d3; li = i - OFF3; }
  else               { src = s4; dst = d4; li = i - OFF4; }
  float4 v = *((const float4*)src + li);
  uint2 ph;
  ph.x = (uint32_t)__half_as_ushort(__float2half_rn(v.x)) |
         ((uint32_t)__half_as_ushort(__float2half_rn(v.y)) << 16);
  ph.y = (uint32_t)__half_as_ushort(__float2half_rn(v.z)) |
         ((uint32_t)__half_as_ushort(__float2half_rn(v.w)) << 16);
  *((uint2*)dst + li) = ph;
}

// ---------------- fused attention prep: RoPE(Q,K) + V-transpose, one launch ----------------
#define QPAIRS (S_LEN * (QDIM / 2))
#define KPAIRS (S_LEN * (KVDIM / 2))
#define ROPE_BLOCKS ((QPAIRS + KPAIRS) / 256)          // 10240
#define VT_BLOCKS   ((KVDIM / 32) * (S_LEN / 32))       // 1024

__global__ void prep_attn_kernel(const float* __restrict__ Qf, const float* __restrict__ Kf,
                                 const float* __restrict__ Vf,
                                 const float* __restrict__ cosb, const float* __restrict__ sinb,
                                 __half* __restrict__ Q16, __half* __restrict__ K16,
                                 __half* __restrict__ Vt16) {
  __shared__ float tile[32][33];
  const int bid = blockIdx.x;
  const int tid = threadIdx.x;
  if (bid < ROPE_BLOCKS) {
    int idx = bid * 256 + tid;
    const float* X;
    __half* X16;
    int width, pairsPerRow;
    if (idx < QPAIRS) { X = Qf; X16 = Q16; width = QDIM; pairsPerRow = QDIM >> 1; }
    else {
      idx -= QPAIRS;
      X = Kf; X16 = K16; width = KVDIM; pairsPerRow = KVDIM >> 1;
    }
    int s = idx / pairsPerRow;
    int p = idx - s * pairsPerRow;
    int head = p >> 5;
    int d = p & 31;
    int c1 = head * HDIM + d;
    float c   = cosb[s * HDIM + d];
    float sn  = sinb[s * HDIM + d];
    float c2  = cosb[s * HDIM + d + 32];
    float sn2 = sinb[s * HDIM + d + 32];
    size_t base = (size_t)s * width;
    float x1 = X[base + c1];
    float x2 = X[base + c1 + 32];
    X16[base + c1]      = __float2half_rn(x1 * c  - x2 * sn);
    X16[base + c1 + 32] = __float2half_rn(x2 * c2 + x1 * sn2);
  } else {
    int u = bid - ROPE_BLOCKS;
    int c0 = (u & 15) << 5;
    int s0 = (u >> 4) << 5;
    int tx = tid & 31, ty = tid >> 5;
#pragma unroll
    for (int i = 0; i < 4; i++)
      tile[ty + i * 8][tx] = Vf[(size_t)(s0 + ty + i * 8) * KVDIM + c0 + tx];
    __syncthreads();
#pragma unroll
    for (int i = 0; i < 4; i++) {
      int r = ty + i * 8;
      Vt16[(size_t)(c0 + r) * S_LEN + s0 + tx] = __float2half_rn(tile[tx][r]);
    }
  }
}

// ---------------- lambda ----------------
__global__ void lam_kernel(const float* __restrict__ lq1, const float* __restrict__ lk1,
                           const float* __restrict__ lq2, const float* __restrict__ lk2) {
  int d = threadIdx.x;
  float s1 = lq1[d] * lk1[d] + lq1[d + 32] * lk1[d + 32];
  float s2 = lq2[d] * lk2[d] + lq2[d + 32] * lk2[d + 32];
#pragma unroll
  for (int off = 16; off > 0; off >>= 1) {
    s1 += __shfl_xor_sync(0xffffffffu, s1, off);
    s2 += __shfl_xor_sync(0xffffffffu, s2, off);
  }
  if (d == 0) g_lam = expf(s1) - expf(s2) + LAMBDA_INIT;
}

// ---------------- HMMA flash attention: plain fp16, 1 CTA/SM (no spills) ----------------
#define ATT_ST   18432
#define ATT_STGB 27648
#define ATT_SMEM (18432 + 2 * 27648)    // 73728

__global__ __launch_bounds__(256, 1) void flash_attn_hmma(
    const __half* __restrict__ Q16, const __half* __restrict__ K16,
    const __half* __restrict__ Vt16, float* __restrict__ O) {
  extern __shared__ char sm[];
  const uint32_t sb = smem_u32(sm);
  const int tid = threadIdx.x;
  const int w = tid >> 5, lane = tid & 31;
  const int h = blockIdx.y;
  const int qb = 15 - (int)blockIdx.x;
  const int q0 = qb << 7;
  const int kh = h >> 2;
  const int ii = h & 15;
  const int vh0 = ii >> 2, vh1 = 4 + (ii >> 2);
  const int nk = 2 * qb + 2;

  auto load_stage = [&](int k0, uint32_t stg) {
#pragma unroll
    for (int i = 0; i < 6; i++) {
      int id = tid + (i << 8);
      if (id < 512) {
        int row = id >> 3, ch = id & 7;
        const __half* src = K16 + (size_t)(k0 + row) * KVDIM + kh * HDIM + ch * 8;
        CP_ASYNC16(stg + row * 144 + ch * 16, src);
      } else {
        int t = id - 512;
        int row = t >> 3, ch = t & 7;
        int grow = (row < 64) ? (vh0 * HDIM + row) : (vh1 * HDIM + row - 64);
        const __half* src = Vt16 + (size_t)grow * S_LEN + k0 + ch * 8;
        CP_ASYNC16(stg + 9216 + row * 144 + ch * 16, src);
      }
    }
  };

  {
#pragma unroll
    for (int i = 0; i < 4; i++) {
      int id = tid + (i << 8);
      int row = id >> 3, ch = id & 7;
      const __half* src = Q16 + (size_t)(q0 + row) * QDIM + h * HDIM + ch * 8;
      CP_ASYNC16(sb + row * 144 + ch * 16, src);
    }
    load_stage(0, sb + ATT_ST);
    CP_COMMIT();
    CP_WAIT0();
  }
  __syncthreads();

  uint32_t qf[4][4];
#pragma unroll
  for (int s = 0; s < 4; s++) {
    uint32_t a = sb + (uint32_t)(w * 16 + (lane & 15)) * 144 + ((lane >> 4) << 4) + s * 32;
    LDMATRIX_X4(qf[s][0], qf[s][1], qf[s][2], qf[s][3], a);
  }

  float oacc[16][4];
#pragma unroll
  for (int n = 0; n < 16; n++)
#pragma unroll
    for (int c = 0; c < 4; c++) oacc[n][c] = 0.f;
  float m0r = -1e30f, m1r = -1e30f, l0r = 0.f, l1r = 0.f;
  const int rmin = q0 + w * 16;
  const int rmax = rmin + 15;
  const int r0g = rmin + (lane >> 2);
  const int r1g = r0g + 8;

  for (int kb = 0; kb < nk; kb++) {
    const int k0 = kb << 6;
    const uint32_t stg = sb + ATT_ST + (uint32_t)(kb & 1) * ATT_STGB;
    if (kb + 1 < nk) {
      load_stage((kb + 1) << 6, sb + ATT_ST + (uint32_t)((kb + 1) & 1) * ATT_STGB);
      CP_COMMIT();
    }

    if (k0 <= rmax) {
      float sacc[8][4];
#pragma unroll
      for (int j = 0; j < 8; j++)
#pragma unroll
        for (int c = 0; c < 4; c++) sacc[j][c] = 0.f;

#pragma unroll
      for (int j = 0; j < 8; j++) {
        uint32_t bh[2][4];
#pragma unroll
        for (int s2 = 0; s2 < 2; s2++) {
          uint32_t a = stg + (uint32_t)(j * 8 + (lane & 7)) * 144 + s2 * 64 + ((lane >> 3) & 3) * 16;
          LDMATRIX_X4(bh[s2][0], bh[s2][1], bh[s2][2], bh[s2][3], a);
        }
#pragma unroll
        for (int s = 0; s < 4; s++) {
          uint32_t b0 = bh[s >> 1][(s & 1) * 2], b1 = bh[s >> 1][(s & 1) * 2 + 1];
          MMA16816H(sacc[j][0], sacc[j][1], sacc[j][2], sacc[j][3],
                    qf[s][0], qf[s][1], qf[s][2], qf[s][3], b0, b1);
        }
      }

      const bool needmask = (k0 + 63) > rmin;
#pragma unroll
      for (int j = 0; j < 8; j++) {
        int cb = k0 + j * 8 + ((lane & 3) << 1);
        sacc[j][0] *= 0.125f; sacc[j][1] *= 0.125f;
        sacc[j][2] *= 0.125f; sacc[j][3] *= 0.125f;
        if (needmask) {
          if (cb     > r0g) sacc[j][0] = -1e30f;
          if (cb + 1 > r0g) sacc[j][1] = -1e30f;
          if (cb     > r1g) sacc[j][2] = -1e30f;
          if (cb + 1 > r1g) sacc[j][3] = -1e30f;
        }
      }

      float mx0 = -1e30f, mx1 = -1e30f;
#pragma unroll
      for (int j = 0; j < 8; j++) {
        mx0 = fmaxf(mx0, fmaxf(sacc[j][0], sacc[j][1]));
        mx1 = fmaxf(mx1, fmaxf(sacc[j][2], sacc[j][3]));
      }
      mx0 = fmaxf(mx0, __shfl_xor_sync(0xffffffffu, mx0, 1));
      mx0 = fmaxf(mx0, __shfl_xor_sync(0xffffffffu, mx0, 2));
      mx1 = fmaxf(mx1, __shfl_xor_sync(0xffffffffu, mx1, 1));
      mx1 = fmaxf(mx1, __shfl_xor_sync(0xffffffffu, mx1, 2));
      float mn0 = fmaxf(m0r, mx0), mn1 = fmaxf(m1r, mx1);
      float al0 = __expf(m0r - mn0), al1 = __expf(m1r - mn1);
      m0r = mn0; m1r = mn1;

      float sum0 = 0.f, sum1 = 0.f;
      uint32_t ph[8][2];
#pragma unroll
      for (int j = 0; j < 8; j++) {
        float p0 = __expf(sacc[j][0] - mn0);
        float p1 = __expf(sacc[j][1] - mn0);
        float p2 = __expf(sacc[j][2] - mn1);
        float p3 = __expf(sacc[j][3] - mn1);
        sum0 += p0 + p1; sum1 += p2 + p3;
        ph[j][0] = pack2h(p0, p1);
        ph[j][1] = pack2h(p2, p3);
      }
      sum0 += __shfl_xor_sync(0xffffffffu, sum0, 1);
      sum0 += __shfl_xor_sync(0xffffffffu, sum0, 2);
      sum1 += __shfl_xor_sync(0xffffffffu, sum1, 1);
      sum1 += __shfl_xor_sync(0xffffffffu, sum1, 2);
      l0r = l0r * al0 + sum0;
      l1r = l1r * al1 + sum1;
#pragma unroll
      for (int n = 0; n < 16; n++) {
        oacc[n][0] *= al0; oacc[n][1] *= al0;
        oacc[n][2] *= al1; oacc[n][3] *= al1;
      }

#pragma unroll
      for (int n = 0; n < 16; n++) {
        uint32_t vh[2][4];
#pragma unroll
        for (int s2 = 0; s2 < 2; s2++) {
          uint32_t a = stg + 9216 + (uint32_t)(n * 8 + (lane & 7)) * 144 + s2 * 64 + ((lane >> 3) & 3) * 16;
          LDMATRIX_X4(vh[s2][0], vh[s2][1], vh[s2][2], vh[s2][3], a);
        }
#pragma unroll
        for (int t = 0; t < 4; t++) {
          uint32_t a0 = ph[2 * t][0], a1 = ph[2 * t][1], a2 = ph[2 * t + 1][0], a3 = ph[2 * t + 1][1];
          uint32_t b0 = vh[t >> 1][(t & 1) * 2], b1 = vh[t >> 1][(t & 1) * 2 + 1];
          MMA16816H(oacc[n][0], oacc[n][1], oacc[n][2], oacc[n][3], a0, a1, a2, a3, b0, b1);
        }
      }
    }

    CP_WAIT0();
    __syncthreads();
  }

  float i0 = 1.f / l0r, i1 = 1.f / l1r;
#pragma unroll
  for (int n = 0; n < 16; n++) {
    int col = n * 8 + ((lane & 3) << 1);
    *(float2*)(O + ((size_t)h * S_LEN + r0g) * VD + col) = make_float2(oacc[n][0] * i0, oacc[n][1] * i0);
    *(float2*)(O + ((size_t)h * S_LEN + r1g) * VD + col) = make_float2(oacc[n][2] * i1, oacc[n][3] * i1);
  }
}

// ---------------- differential combine + RMS norm -> single fp16 ----------------
__global__ void combine_kernel(const float* __restrict__ O, __half* __restrict__ Ac16) {
  const int s = blockIdx.x;
  const int i = blockIdx.y;
  const int d = threadIdx.x;
  const float lam = g_lam;
  float o1 = O[((size_t)i * S_LEN + s) * VD + d];
  float o2 = O[((size_t)(i + 16) * S_LEN + s) * VD + d];
  float a = o1 - lam * o2;
  float ss = a * a;
#pragma unroll
  for (int off = 16; off > 0; off >>= 1)
    ss += __shfl_xor_sync(0xffffffffu, ss, off);
  __shared__ float ws[4];
  int warp = d >> 5, lane = d & 31;
  if (lane == 0) ws[warp] = ss;
  __syncthreads();
  float tot = ws[0] + ws[1] + ws[2] + ws[3];
  float r = rsqrtf(tot * (1.0f / 128.0f) + 1e-6f);
  float aval = (1.0f - LAMBDA_INIT) * a * r;
  Ac16[(size_t)s * QDIM + i * VD + d] = __float2half_rn(aval);
}

// ---------------- launch ----------------
extern "C" void kernel_launch(void* const* d_in, const int* in_sizes, int n_in,
                              void* d_out, int out_size) {
  const float* hidden = (const float*)d_in[0];
  const float* cosb   = (const float*)d_in[1];
  const float* sinb   = (const float*)d_in[2];
  const float* Wq     = (const float*)d_in[3];
  const float* Wk     = (const float*)d_in[4];
  const float* Wv     = (const float*)d_in[5];
  const float* Wo     = (const float*)d_in[6];
  const float* lq1    = (const float*)d_in[7];
  const float* lk1    = (const float*)d_in[8];
  const float* lq2    = (const float*)d_in[9];
  const float* lk2    = (const float*)d_in[10];
  float* out = (float*)d_out;

  float *Qp, *Kp, *Vp, *Op;
  cudaGetSymbolAddress((void**)&Qp, g_Q);
  cudaGetSymbolAddress((void**)&Kp, g_K);
  cudaGetSymbolAddress((void**)&Vp, g_V);
  cudaGetSymbolAddress((void**)&Op, g_O);
  __half *H16, *Wq16, *Wk16, *Wv16, *Wo16, *Ac16;
  cudaGetSymbolAddress((void**)&H16, g_H16);
  cudaGetSymbolAddress((void**)&Wq16, g_Wq16);
  cudaGetSymbolAddress((void**)&Wk16, g_Wk16);
  cudaGetSymbolAddress((void**)&Wv16, g_Wv16);
  cudaGetSymbolAddress((void**)&Wo16, g_Wo16);
  cudaGetSymbolAddress((void**)&Ac16, g_Ac16);
  __half *Q16p, *K16p, *Vt16p;
  cudaGetSymbolAddress((void**)&Q16p, g_Q16);
  cudaGetSymbolAddress((void**)&K16p, g_K16);
  cudaGetSymbolAddress((void**)&Vt16p, g_Vt16);

  cudaFuncSetAttribute(hgemm_qkv_kernel, cudaFuncAttributeMaxDynamicSharedMemorySize, GSMEM);
  cudaFuncSetAttribute(hgemm_o_kernel,   cudaFuncAttributeMaxDynamicSharedMemorySize, GSMEM);
  cudaFuncSetAttribute(flash_attn_hmma,  cudaFuncAttributeMaxDynamicSharedMemorySize, ATT_SMEM);

  // single batched convert (capture-safe: pointers are kernel args)
  f2h_all_kernel<<<(OFF5 + 255) / 256, 256>>>(hidden, Wq, Wk, Wv, Wo,
                                              H16, Wq16, Wk16, Wv16, Wo16);

  // lambda (independent)
  lam_kernel<<<1, 32>>>(lq1, lk1, lq2, lk2);

  // QKV projections (plain fp16, flat 384-CTA grid)
  hgemm_qkv_kernel<<<384, 256, GSMEM>>>(H16, Wq16, Wk16, Wv16, Qp, Kp, Vp);

  // fused prep: RoPE(Q,K) + V transpose in one launch
  prep_attn_kernel<<<ROPE_BLOCKS + VT_BLOCKS, 256>>>(Qp, Kp, Vp, cosb, sinb, Q16p, K16p, Vt16p);

  // attention (plain fp16 HMMA, 1 CTA/SM)
  flash_attn_hmma<<<dim3(16, NHEADS), 256, ATT_SMEM>>>(Q16p, K16p, Vt16p, Op);

  // combine + RMS norm -> fp16 A
  combine_kernel<<<dim3(S_LEN, 16), 128>>>(Op, Ac16);

  // output projection (plain fp16)
  hgemm_o_kernel<<<dim3(QDIM / 128, S_LEN / 128), 256, GSMEM>>>(Ac16, Wo16, out);
}